// round 6
// baseline (speedup 1.0000x reference)
#include <cuda_runtime.h>
#include <math.h>

#define EPSV 1e-20f

#define BB 16
#define H0 352
#define W0 1216
#define H1 176
#define W1 608
#define H2 88
#define W2 304
#define H3 44
#define W3 152

#define P0 (H0*W0)
#define P1 (H1*W1)
#define P2 (H2*W2)
#define P3 (H3*W3)

#define N0 ((size_t)BB*2*P0)
#define N1 ((size_t)BB*2*P1)
#define N2 ((size_t)BB*2*P2)
#define N3 ((size_t)BB*2*P3)

typedef unsigned long long ull;

__device__ float g_scratch[6*N0 + 6*N1 + 6*N2 + 4*N3];
__device__ ull   g_wd[480];
__device__ float g_ws[32];

__constant__ ull   c_wd[480];
__constant__ float c_ws[32];

// dup-pair weight layout (ull units):
// w1:0(50) w2:50(100) w3:150(100) w4:250(72) w5:322(72) w6:394(72) w7:466(4)
// entry: OFF + (ci*K + k)*2 + cout
// c_ws: sums at [2*lyr + co], biases at [16 + 2*lyr + co]

__device__ __forceinline__ ull fma2(ull a, ull b, ull c){
    ull d; asm("fma.rn.f32x2 %0, %1, %2, %3;" : "=l"(d) : "l"(a), "l"(b), "l"(c)); return d;
}
__device__ __forceinline__ void unpack2(ull v, float &a, float &b){
    asm("mov.b64 {%0,%1}, %2;" : "=f"(a), "=f"(b) : "l"(v));
}
__device__ __forceinline__ ull dupf(float w){
    float2 f2 = make_float2(w, w);
    return *(ull*)&f2;
}
__device__ __forceinline__ float sp10(float p){
    float z = 10.0f * p;
    float r = (z > 20.0f) ? z : log1pf(expf(z));
    return r * 0.1f;
}

__global__ void k_prep(const float* __restrict__ w1, const float* __restrict__ b1,
                       const float* __restrict__ w2, const float* __restrict__ b2,
                       const float* __restrict__ w3, const float* __restrict__ b3,
                       const float* __restrict__ w4, const float* __restrict__ b4,
                       const float* __restrict__ w5, const float* __restrict__ b5,
                       const float* __restrict__ w6, const float* __restrict__ b6,
                       const float* __restrict__ w7, const float* __restrict__ b7){
    const float* wp[7]={w1,w2,w3,w4,w5,w6,w7};
    const float* bp[7]={b1,b2,b3,b4,b5,b6,b7};
    const int cin[7]={1,2,2,4,4,4,2};
    const int kk [7]={25,25,25,9,9,9,1};
    const int co [7]={2,2,2,2,2,2,1};
    const int off[7]={0,50,150,250,322,394,466};
    int t=threadIdx.x;
    for(int l=0;l<7;l++){
        int n=cin[l]*kk[l];
        int tot=n*co[l];
        for(int i=t;i<tot;i+=blockDim.x){
            int c=i/n, e=i%n;
            g_wd[off[l]+e*2+c]=dupf(sp10(wp[l][c*n+e]));
        }
    }
    __syncthreads();
    if(t==0){
        for(int l=0;l<7;l++){
            int n=cin[l]*kk[l];
            for(int c=0;c<co[l];c++){
                float s=0.f;
                for(int e=0;e<n;e++){ float lo,hi; unpack2(g_wd[off[l]+e*2+c],lo,hi); s+=lo; }
                g_ws[2*l+c]=s;
                g_ws[16+2*l+c]=bp[l][c];
            }
        }
    }
}

// ---------------- tiled 5x5 nconv, const weights, 4x2/thread ---------------
#define TX5 64
#define TY5 16
#define SW5 (TX5+4)   // 68
#define SH5 (TY5+4)   // 20

template<int CIN, int WOFF, int LYR>
__global__ void __launch_bounds__(128)
k_nconv5t(const float* __restrict__ xin, const float* __restrict__ cin,
          float* __restrict__ xout, float* __restrict__ cout_,
          int H, int W, int bpr, int bpc){
    __shared__ __align__(16) float2 sm[CIN][SH5*SW5];

    const int t = threadIdx.x;
    const int P = H*W;

    int bx = blockIdx.x % bpr;
    int tmp = blockIdx.x / bpr;
    int by = tmp % bpc;
    int b  = tmp / bpc;
    int gx0 = bx*TX5 - 2;
    int gy0 = by*TY5 - 2;

    const bool inter = (gx0>=0) && (gy0>=0) && (gx0+SW5<=W) && (gy0+SH5<=H);
    const int fx = t & 31, fy = t >> 5;

    #pragma unroll
    for(int ci=0;ci<CIN;ci++){
        const float* cb = cin + (size_t)(b*CIN+ci)*P;
        const float* xb = xin + (size_t)(b*CIN+ci)*P;
        if(inter){
            #pragma unroll
            for(int ly=0;ly<SH5;ly+=4){
                int row = (gy0+ly+fy)*W + gx0;
                int so  = (ly+fy)*SW5;
                for(int lx=fx; lx<SW5; lx+=32){
                    float c = cb[row+lx];
                    sm[ci][so+lx] = make_float2(c, xb[row+lx]*c);
                }
            }
        } else {
            #pragma unroll
            for(int ly=0;ly<SH5;ly+=4){
                int gy = gy0+ly+fy;
                int so = (ly+fy)*SW5;
                for(int lx=fx; lx<SW5; lx+=32){
                    int gx = gx0+lx;
                    float c=0.f, d=0.f;
                    if((unsigned)gx<(unsigned)W && (unsigned)gy<(unsigned)H){
                        int o = gy*W+gx;
                        c = cb[o]; d = xb[o]*c;
                    }
                    sm[ci][so+lx] = make_float2(c, d);
                }
            }
        }
    }
    __syncthreads();

    const int tx = (t & 15)*4;
    const int ty = (t >> 4)*2;

    ull acc[2][2][4];
    #pragma unroll
    for(int a=0;a<2;a++)
      #pragma unroll
      for(int dy=0;dy<2;dy++)
        #pragma unroll
        for(int dx=0;dx<4;dx++) acc[a][dy][dx]=0ull;

    #pragma unroll
    for(int ci=0;ci<CIN;ci++){
        #pragma unroll
        for(int r=0;r<6;r++){
            ull v[8];
            const longlong2* p = (const longlong2*)&sm[ci][(ty+r)*SW5 + tx];
            #pragma unroll
            for(int j=0;j<4;j++){ longlong2 q=p[j]; v[2*j]=(ull)q.x; v[2*j+1]=(ull)q.y; }
            if(r<=4){   // dy=0, ky=r
                #pragma unroll
                for(int kx=0;kx<5;kx++){
                    ull wa = c_wd[WOFF + (ci*25 + r*5 + kx)*2];
                    ull wb = c_wd[WOFF + (ci*25 + r*5 + kx)*2 + 1];
                    #pragma unroll
                    for(int dx=0;dx<4;dx++){
                        acc[0][0][dx]=fma2(wa, v[kx+dx], acc[0][0][dx]);
                        acc[1][0][dx]=fma2(wb, v[kx+dx], acc[1][0][dx]);
                    }
                }
            }
            if(r>=1){   // dy=1, ky=r-1
                #pragma unroll
                for(int kx=0;kx<5;kx++){
                    ull wa = c_wd[WOFF + (ci*25 + (r-1)*5 + kx)*2];
                    ull wb = c_wd[WOFF + (ci*25 + (r-1)*5 + kx)*2 + 1];
                    #pragma unroll
                    for(int dx=0;dx<4;dx++){
                        acc[0][1][dx]=fma2(wa, v[kx+dx], acc[0][1][dx]);
                        acc[1][1][dx]=fma2(wb, v[kx+dx], acc[1][1][dx]);
                    }
                }
            }
        }
    }

    float rs0 = 1.0f/c_ws[2*LYR];
    float rs1 = 1.0f/c_ws[2*LYR+1];
    float bi0 = c_ws[16+2*LYR];
    float bi1 = c_ws[16+2*LYR+1];
    int gx = bx*TX5 + tx;
    if(gx < W){
        #pragma unroll
        for(int dy=0;dy<2;dy++){
            int gy = by*TY5 + ty + dy;
            if(gy>=H) continue;
            #pragma unroll
            for(int a=0;a<2;a++){
                float d0,n0,d1,n1,d2,n2,d3,n3;
                unpack2(acc[a][dy][0], d0, n0);
                unpack2(acc[a][dy][1], d1, n1);
                unpack2(acc[a][dy][2], d2, n2);
                unpack2(acc[a][dy][3], d3, n3);
                float bia = a ? bi1 : bi0;
                float rsa = a ? rs1 : rs0;
                float4 xo = make_float4(n0/(d0+EPSV)+bia, n1/(d1+EPSV)+bia,
                                        n2/(d2+EPSV)+bia, n3/(d3+EPSV)+bia);
                float4 co = make_float4(d0*rsa, d1*rsa, d2*rsa, d3*rsa);
                size_t o = (size_t)(b*2+a)*P + (size_t)gy*W + gx;
                *(float4*)&xout[o]  = xo;
                *(float4*)&cout_[o] = co;
            }
        }
    }
}

// ---------------- tiled 3x3 cat nconv, const weights, 4x2/thread -----------
#define TX3 64
#define TY3 16
#define SW3 (TX3+2)   // 66
#define SH3 (TY3+2)   // 18

template<bool UP_FIRST, int WOFF, int LYR>
__global__ void __launch_bounds__(128)
k_nconv3t(const float* __restrict__ xa, const float* __restrict__ ca,
          const float* __restrict__ xb, const float* __restrict__ cb,
          float* __restrict__ xout, float* __restrict__ cout_,
          int H, int W, int bpr, int bpc){
    __shared__ __align__(16) float2 sm[4][SH3*SW3];

    const int t = threadIdx.x;
    const int P = H*W;
    const int Wh = W>>1, Ph = (W>>1)*(H>>1);

    int bx = blockIdx.x % bpr;
    int tmp = blockIdx.x / bpr;
    int by = tmp % bpc;
    int b  = tmp / bpc;
    int gx0 = bx*TX3 - 1;
    int gy0 = by*TY3 - 1;

    const bool inter = (gx0>=0) && (gy0>=0) && (gx0+SW3<=W) && (gy0+SH3<=H);
    const int fx = t & 31, fy = t >> 5;

    #pragma unroll
    for(int ci=0;ci<4;ci++){
        const bool fromUp = UP_FIRST ? (ci<2) : (ci>=2);
        const int ch = fromUp ? (UP_FIRST ? ci : ci-2) : (UP_FIRST ? ci-2 : ci);
        const float* cs = fromUp ? (cb + (size_t)(b*2+ch)*Ph) : (ca + (size_t)(b*2+ch)*P);
        const float* xs = fromUp ? (xb + (size_t)(b*2+ch)*Ph) : (xa + (size_t)(b*2+ch)*P);
        if(inter){
            #pragma unroll
            for(int ly=0;ly<SH3;ly+=4){
                int gy = gy0+ly+fy;
                int so = (ly+fy)*SW3;
                if(ly+fy < SH3){
                    for(int lx=fx; lx<SW3; lx+=32){
                        int gx = gx0+lx;
                        int o = fromUp ? ((gy>>1)*Wh + (gx>>1)) : (gy*W+gx);
                        float c = cs[o];
                        sm[ci][so+lx] = make_float2(c, xs[o]*c);
                    }
                }
            }
        } else {
            #pragma unroll
            for(int ly=0;ly<SH3;ly+=4){
                int gy = gy0+ly+fy;
                int so = (ly+fy)*SW3;
                if(ly+fy < SH3){
                    for(int lx=fx; lx<SW3; lx+=32){
                        int gx = gx0+lx;
                        float c=0.f, d=0.f;
                        if((unsigned)gx<(unsigned)W && (unsigned)gy<(unsigned)H){
                            int o = fromUp ? ((gy>>1)*Wh + (gx>>1)) : (gy*W+gx);
                            c = cs[o]; d = xs[o]*c;
                        }
                        sm[ci][so+lx] = make_float2(c, d);
                    }
                }
            }
        }
    }
    __syncthreads();

    const int tx = (t & 15)*4;
    const int ty = (t >> 4)*2;

    ull acc[2][2][4];
    #pragma unroll
    for(int a=0;a<2;a++)
      #pragma unroll
      for(int dy=0;dy<2;dy++)
        #pragma unroll
        for(int dx=0;dx<4;dx++) acc[a][dy][dx]=0ull;

    #pragma unroll
    for(int ci=0;ci<4;ci++){
        #pragma unroll
        for(int r=0;r<4;r++){
            ull v[6];
            const longlong2* p = (const longlong2*)&sm[ci][(ty+r)*SW3 + tx];
            #pragma unroll
            for(int j=0;j<3;j++){ longlong2 q=p[j]; v[2*j]=(ull)q.x; v[2*j+1]=(ull)q.y; }
            if(r<=2){   // dy=0, ky=r
                #pragma unroll
                for(int kx=0;kx<3;kx++){
                    ull wa = c_wd[WOFF + (ci*9 + r*3 + kx)*2];
                    ull wb = c_wd[WOFF + (ci*9 + r*3 + kx)*2 + 1];
                    #pragma unroll
                    for(int dx=0;dx<4;dx++){
                        acc[0][0][dx]=fma2(wa, v[kx+dx], acc[0][0][dx]);
                        acc[1][0][dx]=fma2(wb, v[kx+dx], acc[1][0][dx]);
                    }
                }
            }
            if(r>=1){   // dy=1, ky=r-1
                #pragma unroll
                for(int kx=0;kx<3;kx++){
                    ull wa = c_wd[WOFF + (ci*9 + (r-1)*3 + kx)*2];
                    ull wb = c_wd[WOFF + (ci*9 + (r-1)*3 + kx)*2 + 1];
                    #pragma unroll
                    for(int dx=0;dx<4;dx++){
                        acc[0][1][dx]=fma2(wa, v[kx+dx], acc[0][1][dx]);
                        acc[1][1][dx]=fma2(wb, v[kx+dx], acc[1][1][dx]);
                    }
                }
            }
        }
    }

    float rs0 = 1.0f/c_ws[2*LYR];
    float rs1 = 1.0f/c_ws[2*LYR+1];
    float bi0 = c_ws[16+2*LYR];
    float bi1 = c_ws[16+2*LYR+1];
    int gx = bx*TX3 + tx;
    if(gx < W){
        #pragma unroll
        for(int dy=0;dy<2;dy++){
            int gy = by*TY3 + ty + dy;
            if(gy>=H) continue;
            #pragma unroll
            for(int a=0;a<2;a++){
                float d0,n0,d1,n1,d2,n2,d3,n3;
                unpack2(acc[a][dy][0], d0, n0);
                unpack2(acc[a][dy][1], d1, n1);
                unpack2(acc[a][dy][2], d2, n2);
                unpack2(acc[a][dy][3], d3, n3);
                float bia = a ? bi1 : bi0;
                float rsa = a ? rs1 : rs0;
                float4 xo = make_float4(n0/(d0+EPSV)+bia, n1/(d1+EPSV)+bia,
                                        n2/(d2+EPSV)+bia, n3/(d3+EPSV)+bia);
                float4 co = make_float4(d0*rsa, d1*rsa, d2*rsa, d3*rsa);
                size_t o = (size_t)(b*2+a)*P + (size_t)gy*W + gx;
                *(float4*)&xout[o]  = xo;
                *(float4*)&cout_[o] = co;
            }
        }
    }
}

// 2x2 max-pool on conf (first-max, row-major order), gather x at argmax.
__global__ void k_pool(const float* __restrict__ cin, const float* __restrict__ xin,
                       float* __restrict__ cds, float* __restrict__ xds,
                       int Hh, int Wh){
    int idx = blockIdx.x*blockDim.x + threadIdx.x;
    int total = BB*2*Hh*Wh;
    if(idx >= total) return;
    int x = idx % Wh;
    int y = (idx / Wh) % Hh;
    int pl = idx / (Hh*Wh);
    int Wi = Wh*2;
    size_t base = (size_t)pl*(Hh*2)*Wi + (size_t)(2*y)*Wi + 2*x;
    float2 ct = *(const float2*)(cin+base);
    float2 cbm= *(const float2*)(cin+base+Wi);
    float2 xt = *(const float2*)(xin+base);
    float2 xbm= *(const float2*)(xin+base+Wi);
    float best=ct.x, bx=xt.x;
    if(ct.y >best){best=ct.y; bx=xt.y;}
    if(cbm.x>best){best=cbm.x;bx=xbm.x;}
    if(cbm.y>best){best=cbm.y;bx=xbm.y;}
    cds[idx]=best*0.25f;
    xds[idx]=bx;
}

// final 1x1 nconv, float4-vectorized, const weights
__global__ void k_nconv1x1(const float* __restrict__ xin, const float* __restrict__ cin,
                           float* __restrict__ xout, float* __restrict__ cout_){
    int idx = blockIdx.x*blockDim.x + threadIdx.x;
    const int Q = P0/4;
    if(idx >= BB*Q) return;
    int q = idx % Q;
    int b = idx / Q;
    const float4* x0p = (const float4*)(xin + (size_t)(b*2+0)*P0) + q;
    const float4* x1p = (const float4*)(xin + (size_t)(b*2+1)*P0) + q;
    const float4* c0p = (const float4*)(cin + (size_t)(b*2+0)*P0) + q;
    const float4* c1p = (const float4*)(cin + (size_t)(b*2+1)*P0) + q;
    float4 X0=*x0p, X1=*x1p, C0=*c0p, C1=*c1p;
    float w0,w1,hi;
    unpack2(c_wd[466], w0, hi);
    unpack2(c_wd[468], w1, hi);
    float rsum = 1.0f/c_ws[12];
    float bi = c_ws[28];
    float4 XO, CO;
    #pragma unroll
    for(int k=0;k<4;k++){
        float c0v = ((const float*)&C0)[k];
        float c1v = ((const float*)&C1)[k];
        float den = w0*c0v + w1*c1v;
        float nom = w0*(((const float*)&X0)[k]*c0v) + w1*(((const float*)&X1)[k]*c1v);
        ((float*)&XO)[k] = nom/(den+EPSV) + bi;
        ((float*)&CO)[k] = den*rsum;
    }
    ((float4*)(xout  + (size_t)b*P0))[q] = XO;
    ((float4*)(cout_ + (size_t)b*P0))[q] = CO;
}

extern "C" void kernel_launch(void* const* d_in, const int* in_sizes, int n_in,
                              void* d_out, int out_size){
    const float* x0 = (const float*)d_in[0];
    const float* c0 = (const float*)d_in[1];
    const float* w1 = (const float*)d_in[2];  const float* b1 = (const float*)d_in[3];
    const float* w2 = (const float*)d_in[4];  const float* b2 = (const float*)d_in[5];
    const float* w3 = (const float*)d_in[6];  const float* b3 = (const float*)d_in[7];
    const float* w4 = (const float*)d_in[8];  const float* b4 = (const float*)d_in[9];
    const float* w5 = (const float*)d_in[10]; const float* b5 = (const float*)d_in[11];
    const float* w6 = (const float*)d_in[12]; const float* b6 = (const float*)d_in[13];
    const float* w7 = (const float*)d_in[14]; const float* b7 = (const float*)d_in[15];

    float* S = nullptr;  cudaGetSymbolAddress((void**)&S,  g_scratch);
    void* gwd = nullptr; cudaGetSymbolAddress(&gwd, g_wd);
    void* gws = nullptr; cudaGetSymbolAddress(&gws, g_ws);

    float *xA=S,   *cA=S+N0,   *xB=S+2*N0, *cB=S+3*N0, *x1=S+4*N0, *c1=S+5*N0;
    float *Sh = S + 6*N0;
    float *xha=Sh, *cha=Sh+N1, *xhb=Sh+2*N1, *chb=Sh+3*N1, *x2d=Sh+4*N1, *c2d=Sh+5*N1;
    float *Sq = Sh + 6*N1;
    float *xq=Sq,  *cq=Sq+N2,  *x3d=Sq+2*N2, *c3d=Sq+3*N2, *x34=Sq+4*N2, *c34=Sq+5*N2;
    float *Se = Sq + 6*N2;
    float *xe=Se,  *ce=Se+N3,  *x4=Se+2*N3,  *c4=Se+3*N3;

    const int thr = 256;
    auto gb = [&](long n){ return (int)((n + thr - 1) / thr); };
    auto tiles = [&](int H, int W, int &bpr, int &bpc)->int{
        bpr = (W + TX5 - 1)/TX5; bpc = (H + TY5 - 1)/TY5;
        return bpr*bpc*BB;
    };

    k_prep<<<1,128>>>(w1,b1,w2,b2,w3,b3,w4,b4,w5,b5,w6,b6,w7,b7);
    cudaMemcpyToSymbolAsync(c_wd, gwd, sizeof(ull)*480,  0, cudaMemcpyDeviceToDevice, 0);
    cudaMemcpyToSymbolAsync(c_ws, gws, sizeof(float)*32, 0, cudaMemcpyDeviceToDevice, 0);

    int bpr, bpc, g;

    // encoder full res
    g = tiles(H0,W0,bpr,bpc);
    k_nconv5t<1,0,0>  <<<g,128>>>(x0, c0, xA, cA, H0, W0, bpr, bpc);
    k_nconv5t<2,50,1> <<<g,128>>>(xA, cA, xB, cB, H0, W0, bpr, bpc);
    k_nconv5t<2,150,2><<<g,128>>>(xB, cB, x1, c1, H0, W0, bpr, bpc);

    // level 1
    k_pool<<<gb((long)BB*2*P1),thr>>>(c1, x1, cha, xha, H1, W1);
    g = tiles(H1,W1,bpr,bpc);
    k_nconv5t<2,50,1> <<<g,128>>>(xha, cha, xhb, chb, H1, W1, bpr, bpc);
    k_nconv5t<2,150,2><<<g,128>>>(xhb, chb, x2d, c2d, H1, W1, bpr, bpc);

    // level 2
    k_pool<<<gb((long)BB*2*P2),thr>>>(c2d, x2d, cq, xq, H2, W2);
    g = tiles(H2,W2,bpr,bpc);
    k_nconv5t<2,50,1> <<<g,128>>>(xq, cq, x3d, c3d, H2, W2, bpr, bpc);

    // level 3
    k_pool<<<gb((long)BB*2*P3),thr>>>(c3d, x3d, ce, xe, H3, W3);
    g = tiles(H3,W3,bpr,bpc);
    k_nconv5t<2,50,1> <<<g,128>>>(xe, ce, x4, c4, H3, W3, bpr, bpc);

    // decoder
    g = tiles(H2,W2,bpr,bpc);
    k_nconv3t<false,250,3><<<g,128>>>(x3d, c3d, x4, c4,   x34, c34, H2, W2, bpr, bpc);
    g = tiles(H1,W1,bpr,bpc);
    k_nconv3t<false,322,4><<<g,128>>>(x2d, c2d, x34, c34, xha, cha, H1, W1, bpr, bpc);
    g = tiles(H0,W0,bpr,bpc);
    k_nconv3t<true,394,5> <<<g,128>>>(x1, c1, xha, cha,   xA, cA, H0, W0, bpr, bpc);

    float* out = (float*)d_out;
    k_nconv1x1<<<gb((long)BB*(P0/4)),thr>>>(xA, cA, out, out + (size_t)BB*P0);
}

// round 7
// speedup vs baseline: 1.2865x; 1.2865x over previous
#include <cuda_runtime.h>
#include <math.h>

#define EPSV 1e-20f

#define BB 16
#define H0 352
#define W0 1216
#define H1 176
#define W1 608
#define H2 88
#define W2 304
#define H3 44
#define W3 152

#define P0 (H0*W0)
#define P1 (H1*W1)
#define P2 (H2*W2)
#define P3 (H3*W3)

#define N0 ((size_t)BB*2*P0)
#define N1 ((size_t)BB*2*P1)
#define N2 ((size_t)BB*2*P2)
#define N3 ((size_t)BB*2*P3)

typedef unsigned long long ull;

__device__ float g_scratch[6*N0 + 6*N1 + 6*N2 + 4*N3];
__device__ ull   g_wd[480];
__device__ float g_ws[32];

// dup-pair weight layout (ull units):
// w1:0(50) w2:50(100) w3:150(100) w4:250(72) w5:322(72) w6:394(72) w7:466(4)
// entry: OFF + (ci*K + k)*2 + cout
// g_ws: sums at [2*lyr + co], biases at [16 + 2*lyr + co]

__device__ __forceinline__ ull fma2(ull a, ull b, ull c){
    ull d; asm("fma.rn.f32x2 %0, %1, %2, %3;" : "=l"(d) : "l"(a), "l"(b), "l"(c)); return d;
}
__device__ __forceinline__ void unpack2(ull v, float &a, float &b){
    asm("mov.b64 {%0,%1}, %2;" : "=f"(a), "=f"(b) : "l"(v));
}
__device__ __forceinline__ ull dupf(float w){
    float2 f2 = make_float2(w, w);
    return *(ull*)&f2;
}
__device__ __forceinline__ float sp10(float p){
    float z = 10.0f * p;
    float r = (z > 20.0f) ? z : log1pf(expf(z));
    return r * 0.1f;
}

__global__ void k_prep(const float* __restrict__ w1, const float* __restrict__ b1,
                       const float* __restrict__ w2, const float* __restrict__ b2,
                       const float* __restrict__ w3, const float* __restrict__ b3,
                       const float* __restrict__ w4, const float* __restrict__ b4,
                       const float* __restrict__ w5, const float* __restrict__ b5,
                       const float* __restrict__ w6, const float* __restrict__ b6,
                       const float* __restrict__ w7, const float* __restrict__ b7){
    const float* wp[7]={w1,w2,w3,w4,w5,w6,w7};
    const float* bp[7]={b1,b2,b3,b4,b5,b6,b7};
    const int cin[7]={1,2,2,4,4,4,2};
    const int kk [7]={25,25,25,9,9,9,1};
    const int co [7]={2,2,2,2,2,2,1};
    const int off[7]={0,50,150,250,322,394,466};
    int t=threadIdx.x;
    for(int l=0;l<7;l++){
        int n=cin[l]*kk[l];
        int tot=n*co[l];
        for(int i=t;i<tot;i+=blockDim.x){
            int c=i/n, e=i%n;
            g_wd[off[l]+e*2+c]=dupf(sp10(wp[l][c*n+e]));
        }
    }
    __syncthreads();
    if(t==0){
        for(int l=0;l<7;l++){
            int n=cin[l]*kk[l];
            for(int c=0;c<co[l];c++){
                float s=0.f;
                for(int e=0;e<n;e++){ float lo,hi; unpack2(g_wd[off[l]+e*2+c],lo,hi); s+=lo; }
                g_ws[2*l+c]=s;
                g_ws[16+2*l+c]=bp[l][c];
            }
        }
    }
}

// ---------------- tiled 5x5 nconv, smem weights, 4x2/thread, opt. fused pool
#define TX5 64
#define TY5 16
#define SW5 (TX5+4)   // 68
#define SH5 (TY5+4)   // 20

template<int CIN, int WOFF, int LYR, bool POOL>
__global__ void __launch_bounds__(128)
k_nconv5t(const float* __restrict__ xin, const float* __restrict__ cin,
          float* __restrict__ xout, float* __restrict__ cout_,
          float* __restrict__ xds, float* __restrict__ cds,
          int H, int W, int bpr, int bpc){
    __shared__ __align__(16) float2 sm[CIN][SH5*SW5];
    __shared__ __align__(16) ull wpk2[2*CIN*25];
    __shared__ float wex[4];

    const int t = threadIdx.x;
    const int P = H*W;

    for(int i=t;i<2*CIN*25;i+=128) wpk2[i]=g_wd[WOFF+i];
    if(t<2){ wex[t]=g_ws[2*LYR+t]; wex[2+t]=g_ws[16+2*LYR+t]; }

    int bx = blockIdx.x % bpr;
    int tmp = blockIdx.x / bpr;
    int by = tmp % bpc;
    int b  = tmp / bpc;
    int gx0 = bx*TX5 - 2;
    int gy0 = by*TY5 - 2;

    #pragma unroll
    for(int ci=0;ci<CIN;ci++){
        const float* cb = cin + (size_t)(b*CIN+ci)*P;
        const float* xb = xin + (size_t)(b*CIN+ci)*P;
        for(int i=t;i<SH5*SW5;i+=128){
            int lx = i % SW5, ly = i / SW5;
            int gx = gx0+lx, gy = gy0+ly;
            float c=0.f, d=0.f;
            if((unsigned)gx<(unsigned)W && (unsigned)gy<(unsigned)H){
                int o = gy*W+gx;
                c = cb[o]; d = xb[o]*c;
            }
            sm[ci][i] = make_float2(c, d);
        }
    }
    __syncthreads();

    const int tx = (t & 15)*4;
    const int ty = (t >> 4)*2;

    ull acc[2][2][4];
    #pragma unroll
    for(int a=0;a<2;a++)
      #pragma unroll
      for(int dy=0;dy<2;dy++)
        #pragma unroll
        for(int dx=0;dx<4;dx++) acc[a][dy][dx]=0ull;

    #pragma unroll
    for(int ci=0;ci<CIN;ci++){
        #pragma unroll
        for(int r=0;r<6;r++){
            ull v[8];
            const longlong2* p = (const longlong2*)&sm[ci][(ty+r)*SW5 + tx];
            #pragma unroll
            for(int j=0;j<4;j++){ longlong2 q=p[j]; v[2*j]=(ull)q.x; v[2*j+1]=(ull)q.y; }
            if(r<=4){   // dy=0, ky=r
                #pragma unroll
                for(int kx=0;kx<5;kx++){
                    longlong2 wp = *(const longlong2*)&wpk2[(ci*25 + r*5 + kx)*2];
                    ull wa=(ull)wp.x, wb=(ull)wp.y;
                    #pragma unroll
                    for(int dx=0;dx<4;dx++){
                        acc[0][0][dx]=fma2(wa, v[kx+dx], acc[0][0][dx]);
                        acc[1][0][dx]=fma2(wb, v[kx+dx], acc[1][0][dx]);
                    }
                }
            }
            if(r>=1){   // dy=1, ky=r-1
                #pragma unroll
                for(int kx=0;kx<5;kx++){
                    longlong2 wp = *(const longlong2*)&wpk2[(ci*25 + (r-1)*5 + kx)*2];
                    ull wa=(ull)wp.x, wb=(ull)wp.y;
                    #pragma unroll
                    for(int dx=0;dx<4;dx++){
                        acc[0][1][dx]=fma2(wa, v[kx+dx], acc[0][1][dx]);
                        acc[1][1][dx]=fma2(wb, v[kx+dx], acc[1][1][dx]);
                    }
                }
            }
        }
    }

    float rs0 = 1.0f/wex[0];
    float rs1 = 1.0f/wex[1];
    int gx = bx*TX5 + tx;
    int gyp = by*TY5 + ty;        // even; rows gyp, gyp+1
    if(gx < W && gyp < H){
        const int Wh = W>>1;
        const int Ph = Wh*(H>>1);
        #pragma unroll
        for(int a=0;a<2;a++){
            float rsa = a ? rs1 : rs0;
            float bia = wex[2+a];
            float rx[2][4], rc[2][4];
            #pragma unroll
            for(int dy=0;dy<2;dy++){
                #pragma unroll
                for(int j=0;j<2;j++){
                    float d0,n0,d1,n1;
                    unpack2(acc[a][dy][2*j],   d0, n0);
                    unpack2(acc[a][dy][2*j+1], d1, n1);
                    rx[dy][2*j]   = n0/(d0+EPSV)+bia;
                    rx[dy][2*j+1] = n1/(d1+EPSV)+bia;
                    rc[dy][2*j]   = d0*rsa;
                    rc[dy][2*j+1] = d1*rsa;
                }
                size_t o = (size_t)(b*2+a)*P + (size_t)(gyp+dy)*W + gx;
                *(float4*)&xout[o]  = make_float4(rx[dy][0],rx[dy][1],rx[dy][2],rx[dy][3]);
                *(float4*)&cout_[o] = make_float4(rc[dy][0],rc[dy][1],rc[dy][2],rc[dy][3]);
            }
            if(POOL){
                float2 pc, px;
                #pragma unroll
                for(int cell=0;cell<2;cell++){
                    int c0 = 2*cell;
                    float bc = rc[0][c0],  bxv = rx[0][c0];
                    if(rc[0][c0+1]>bc){ bc=rc[0][c0+1]; bxv=rx[0][c0+1]; }
                    if(rc[1][c0]  >bc){ bc=rc[1][c0];   bxv=rx[1][c0];   }
                    if(rc[1][c0+1]>bc){ bc=rc[1][c0+1]; bxv=rx[1][c0+1]; }
                    ((float*)&pc)[cell] = bc*0.25f;
                    ((float*)&px)[cell] = bxv;
                }
                size_t po = (size_t)(b*2+a)*Ph + (size_t)(gyp>>1)*Wh + (gx>>1);
                *(float2*)&cds[po] = pc;
                *(float2*)&xds[po] = px;
            }
        }
    }
}

// ---------------- tiled 3x3 cat nconv, smem weights, 4x2/thread ------------
#define TX3 64
#define TY3 16
#define SW3 (TX3+2)   // 66
#define SH3 (TY3+2)   // 18

template<bool UP_FIRST, int WOFF, int LYR>
__global__ void __launch_bounds__(128)
k_nconv3t(const float* __restrict__ xa, const float* __restrict__ ca,
          const float* __restrict__ xb, const float* __restrict__ cb,
          float* __restrict__ xout, float* __restrict__ cout_,
          int H, int W, int bpr, int bpc){
    __shared__ __align__(16) float2 sm[4][SH3*SW3];
    __shared__ __align__(16) ull wpk2[72];
    __shared__ float wex[4];

    const int t = threadIdx.x;
    const int P = H*W;
    const int Wh = W>>1, Ph = (W>>1)*(H>>1);

    for(int i=t;i<72;i+=128) wpk2[i]=g_wd[WOFF+i];
    if(t<2){ wex[t]=g_ws[2*LYR+t]; wex[2+t]=g_ws[16+2*LYR+t]; }

    int bx = blockIdx.x % bpr;
    int tmp = blockIdx.x / bpr;
    int by = tmp % bpc;
    int b  = tmp / bpc;
    int gx0 = bx*TX3 - 1;
    int gy0 = by*TY3 - 1;

    #pragma unroll
    for(int ci=0;ci<4;ci++){
        const bool fromUp = UP_FIRST ? (ci<2) : (ci>=2);
        const int ch = fromUp ? (UP_FIRST ? ci : ci-2) : (UP_FIRST ? ci-2 : ci);
        const float* cs = fromUp ? (cb + (size_t)(b*2+ch)*Ph) : (ca + (size_t)(b*2+ch)*P);
        const float* xs = fromUp ? (xb + (size_t)(b*2+ch)*Ph) : (xa + (size_t)(b*2+ch)*P);
        for(int i=t;i<SH3*SW3;i+=128){
            int lx = i % SW3, ly = i / SW3;
            int gx = gx0+lx, gy = gy0+ly;
            float c=0.f, d=0.f;
            if((unsigned)gx<(unsigned)W && (unsigned)gy<(unsigned)H){
                int o = fromUp ? ((gy>>1)*Wh + (gx>>1)) : (gy*W+gx);
                c = cs[o]; d = xs[o]*c;
            }
            sm[ci][i] = make_float2(c, d);
        }
    }
    __syncthreads();

    const int tx = (t & 15)*4;
    const int ty = (t >> 4)*2;

    ull acc[2][2][4];
    #pragma unroll
    for(int a=0;a<2;a++)
      #pragma unroll
      for(int dy=0;dy<2;dy++)
        #pragma unroll
        for(int dx=0;dx<4;dx++) acc[a][dy][dx]=0ull;

    #pragma unroll
    for(int ci=0;ci<4;ci++){
        #pragma unroll
        for(int r=0;r<4;r++){
            ull v[6];
            const longlong2* p = (const longlong2*)&sm[ci][(ty+r)*SW3 + tx];
            #pragma unroll
            for(int j=0;j<3;j++){ longlong2 q=p[j]; v[2*j]=(ull)q.x; v[2*j+1]=(ull)q.y; }
            if(r<=2){   // dy=0, ky=r
                #pragma unroll
                for(int kx=0;kx<3;kx++){
                    longlong2 wp = *(const longlong2*)&wpk2[(ci*9 + r*3 + kx)*2];
                    ull wa=(ull)wp.x, wb=(ull)wp.y;
                    #pragma unroll
                    for(int dx=0;dx<4;dx++){
                        acc[0][0][dx]=fma2(wa, v[kx+dx], acc[0][0][dx]);
                        acc[1][0][dx]=fma2(wb, v[kx+dx], acc[1][0][dx]);
                    }
                }
            }
            if(r>=1){   // dy=1, ky=r-1
                #pragma unroll
                for(int kx=0;kx<3;kx++){
                    longlong2 wp = *(const longlong2*)&wpk2[(ci*9 + (r-1)*3 + kx)*2];
                    ull wa=(ull)wp.x, wb=(ull)wp.y;
                    #pragma unroll
                    for(int dx=0;dx<4;dx++){
                        acc[0][1][dx]=fma2(wa, v[kx+dx], acc[0][1][dx]);
                        acc[1][1][dx]=fma2(wb, v[kx+dx], acc[1][1][dx]);
                    }
                }
            }
        }
    }

    float rs0 = 1.0f/wex[0];
    float rs1 = 1.0f/wex[1];
    float bi0 = wex[2];
    float bi1 = wex[3];
    int gx = bx*TX3 + tx;
    if(gx < W){
        #pragma unroll
        for(int dy=0;dy<2;dy++){
            int gy = by*TY3 + ty + dy;
            if(gy>=H) continue;
            #pragma unroll
            for(int a=0;a<2;a++){
                float d0,n0,d1,n1,d2,n2,d3,n3;
                unpack2(acc[a][dy][0], d0, n0);
                unpack2(acc[a][dy][1], d1, n1);
                unpack2(acc[a][dy][2], d2, n2);
                unpack2(acc[a][dy][3], d3, n3);
                float bia = a ? bi1 : bi0;
                float rsa = a ? rs1 : rs0;
                float4 xo = make_float4(n0/(d0+EPSV)+bia, n1/(d1+EPSV)+bia,
                                        n2/(d2+EPSV)+bia, n3/(d3+EPSV)+bia);
                float4 co = make_float4(d0*rsa, d1*rsa, d2*rsa, d3*rsa);
                size_t o = (size_t)(b*2+a)*P + (size_t)gy*W + gx;
                *(float4*)&xout[o]  = xo;
                *(float4*)&cout_[o] = co;
            }
        }
    }
}

// final 1x1 nconv, float4-vectorized
__global__ void k_nconv1x1(const float* __restrict__ xin, const float* __restrict__ cin,
                           float* __restrict__ xout, float* __restrict__ cout_){
    int idx = blockIdx.x*blockDim.x + threadIdx.x;
    const int Q = P0/4;
    if(idx >= BB*Q) return;
    int q = idx % Q;
    int b = idx / Q;
    const float4* x0p = (const float4*)(xin + (size_t)(b*2+0)*P0) + q;
    const float4* x1p = (const float4*)(xin + (size_t)(b*2+1)*P0) + q;
    const float4* c0p = (const float4*)(cin + (size_t)(b*2+0)*P0) + q;
    const float4* c1p = (const float4*)(cin + (size_t)(b*2+1)*P0) + q;
    float4 X0=*x0p, X1=*x1p, C0=*c0p, C1=*c1p;
    float w0,w1,hi;
    unpack2(g_wd[466], w0, hi);
    unpack2(g_wd[468], w1, hi);
    float rsum = 1.0f/g_ws[12];
    float bi = g_ws[28];
    float4 XO, CO;
    #pragma unroll
    for(int k=0;k<4;k++){
        float c0v = ((const float*)&C0)[k];
        float c1v = ((const float*)&C1)[k];
        float den = w0*c0v + w1*c1v;
        float nom = w0*(((const float*)&X0)[k]*c0v) + w1*(((const float*)&X1)[k]*c1v);
        ((float*)&XO)[k] = nom/(den+EPSV) + bi;
        ((float*)&CO)[k] = den*rsum;
    }
    ((float4*)(xout  + (size_t)b*P0))[q] = XO;
    ((float4*)(cout_ + (size_t)b*P0))[q] = CO;
}

extern "C" void kernel_launch(void* const* d_in, const int* in_sizes, int n_in,
                              void* d_out, int out_size){
    const float* x0 = (const float*)d_in[0];
    const float* c0 = (const float*)d_in[1];
    const float* w1 = (const float*)d_in[2];  const float* b1 = (const float*)d_in[3];
    const float* w2 = (const float*)d_in[4];  const float* b2 = (const float*)d_in[5];
    const float* w3 = (const float*)d_in[6];  const float* b3 = (const float*)d_in[7];
    const float* w4 = (const float*)d_in[8];  const float* b4 = (const float*)d_in[9];
    const float* w5 = (const float*)d_in[10]; const float* b5 = (const float*)d_in[11];
    const float* w6 = (const float*)d_in[12]; const float* b6 = (const float*)d_in[13];
    const float* w7 = (const float*)d_in[14]; const float* b7 = (const float*)d_in[15];

    float* S = nullptr;  cudaGetSymbolAddress((void**)&S,  g_scratch);

    float *xA=S,   *cA=S+N0,   *xB=S+2*N0, *cB=S+3*N0, *x1=S+4*N0, *c1=S+5*N0;
    float *Sh = S + 6*N0;
    float *xha=Sh, *cha=Sh+N1, *xhb=Sh+2*N1, *chb=Sh+3*N1, *x2d=Sh+4*N1, *c2d=Sh+5*N1;
    float *Sq = Sh + 6*N1;
    float *xq=Sq,  *cq=Sq+N2,  *x3d=Sq+2*N2, *c3d=Sq+3*N2, *x34=Sq+4*N2, *c34=Sq+5*N2;
    float *Se = Sq + 6*N2;
    float *xe=Se,  *ce=Se+N3,  *x4=Se+2*N3,  *c4=Se+3*N3;

    auto tiles = [&](int H, int W, int &bpr, int &bpc)->int{
        bpr = (W + TX5 - 1)/TX5; bpc = (H + TY5 - 1)/TY5;
        return bpr*bpc*BB;
    };

    k_prep<<<1,128>>>(w1,b1,w2,b2,w3,b3,w4,b4,w5,b5,w6,b6,w7,b7);

    int bpr, bpc, g;

    // encoder full res (3rd layer fuses pool -> level-1 inputs)
    g = tiles(H0,W0,bpr,bpc);
    k_nconv5t<1,0,0,false>  <<<g,128>>>(x0, c0, xA, cA, nullptr, nullptr, H0, W0, bpr, bpc);
    k_nconv5t<2,50,1,false> <<<g,128>>>(xA, cA, xB, cB, nullptr, nullptr, H0, W0, bpr, bpc);
    k_nconv5t<2,150,2,true> <<<g,128>>>(xB, cB, x1, c1, xha, cha, H0, W0, bpr, bpc);

    // level 1 (2nd layer fuses pool -> level-2 inputs)
    g = tiles(H1,W1,bpr,bpc);
    k_nconv5t<2,50,1,false> <<<g,128>>>(xha, cha, xhb, chb, nullptr, nullptr, H1, W1, bpr, bpc);
    k_nconv5t<2,150,2,true> <<<g,128>>>(xhb, chb, x2d, c2d, xq, cq, H1, W1, bpr, bpc);

    // level 2 (fuses pool -> level-3 inputs)
    g = tiles(H2,W2,bpr,bpc);
    k_nconv5t<2,50,1,true>  <<<g,128>>>(xq, cq, x3d, c3d, xe, ce, H2, W2, bpr, bpc);

    // level 3
    g = tiles(H3,W3,bpr,bpc);
    k_nconv5t<2,50,1,false> <<<g,128>>>(xe, ce, x4, c4, nullptr, nullptr, H3, W3, bpr, bpc);

    // decoder
    g = tiles(H2,W2,bpr,bpc);
    k_nconv3t<false,250,3><<<g,128>>>(x3d, c3d, x4, c4,   x34, c34, H2, W2, bpr, bpc);
    g = tiles(H1,W1,bpr,bpc);
    k_nconv3t<false,322,4><<<g,128>>>(x2d, c2d, x34, c34, xha, cha, H1, W1, bpr, bpc);
    g = tiles(H0,W0,bpr,bpc);
    k_nconv3t<true,394,5> <<<g,128>>>(x1, c1, xha, cha,   xA, cA, H0, W0, bpr, bpc);

    float* out = (float*)d_out;
    k_nconv1x1<<<(BB*(P0/4)+255)/256,256>>>(xA, cA, out, out + (size_t)BB*P0);
}

// round 8
// speedup vs baseline: 1.4759x; 1.1472x over previous
#include <cuda_runtime.h>
#include <math.h>

#define EPSV 1e-20f

#define BB 16
#define H0 352
#define W0 1216
#define H1 176
#define W1 608
#define H2 88
#define W2 304
#define H3 44
#define W3 152

#define P0 (H0*W0)
#define P1 (H1*W1)
#define P2 (H2*W2)
#define P3 (H3*W3)

#define N0 ((size_t)BB*2*P0)
#define N1 ((size_t)BB*2*P1)
#define N2 ((size_t)BB*2*P2)
#define N3 ((size_t)BB*2*P3)

typedef unsigned long long ull;

__device__ float g_scratch[6*N0 + 6*N1 + 6*N2 + 4*N3];
__device__ ull   g_wd[480];
__device__ float g_ws[32];

// dup-pair weight layout (ull units):
// w1:0(50) w2:50(100) w3:150(100) w4:250(72) w5:322(72) w6:394(72) w7:466(4)
// entry: OFF + (ci*K + k)*2 + cout
// g_ws: sums at [2*lyr + co], biases at [16 + 2*lyr + co]

__device__ __forceinline__ ull fma2(ull a, ull b, ull c){
    ull d; asm("fma.rn.f32x2 %0, %1, %2, %3;" : "=l"(d) : "l"(a), "l"(b), "l"(c)); return d;
}
__device__ __forceinline__ void unpack2(ull v, float &a, float &b){
    asm("mov.b64 {%0,%1}, %2;" : "=f"(a), "=f"(b) : "l"(v));
}
__device__ __forceinline__ ull dupf(float w){
    float2 f2 = make_float2(w, w);
    return *(ull*)&f2;
}
__device__ __forceinline__ float sp10(float p){
    float z = 10.0f * p;
    float r = (z > 20.0f) ? z : log1pf(expf(z));
    return r * 0.1f;
}

__global__ void k_prep(const float* __restrict__ w1, const float* __restrict__ b1,
                       const float* __restrict__ w2, const float* __restrict__ b2,
                       const float* __restrict__ w3, const float* __restrict__ b3,
                       const float* __restrict__ w4, const float* __restrict__ b4,
                       const float* __restrict__ w5, const float* __restrict__ b5,
                       const float* __restrict__ w6, const float* __restrict__ b6,
                       const float* __restrict__ w7, const float* __restrict__ b7){
    const float* wp[7]={w1,w2,w3,w4,w5,w6,w7};
    const float* bp[7]={b1,b2,b3,b4,b5,b6,b7};
    const int cin[7]={1,2,2,4,4,4,2};
    const int kk [7]={25,25,25,9,9,9,1};
    const int co [7]={2,2,2,2,2,2,1};
    const int off[7]={0,50,150,250,322,394,466};
    int t=threadIdx.x;
    for(int l=0;l<7;l++){
        int n=cin[l]*kk[l];
        int tot=n*co[l];
        for(int i=t;i<tot;i+=blockDim.x){
            int c=i/n, e=i%n;
            g_wd[off[l]+e*2+c]=dupf(sp10(wp[l][c*n+e]));
        }
    }
    __syncthreads();
    if(t==0){
        for(int l=0;l<7;l++){
            int n=cin[l]*kk[l];
            for(int c=0;c<co[l];c++){
                float s=0.f;
                for(int e=0;e<n;e++){ float lo,hi; unpack2(g_wd[off[l]+e*2+c],lo,hi); s+=lo; }
                g_ws[2*l+c]=s;
                g_ws[16+2*l+c]=bp[l][c];
            }
        }
    }
}

// ---------------- tiled 5x5 nconv, smem weights, 4x2/thread, opt. fused pool
#define TX5 64
#define TY5 16
#define SW5 (TX5+4)   // 68
#define SH5 (TY5+4)   // 20

template<int CIN, int WOFF, int LYR, bool POOL>
__global__ void __launch_bounds__(128,7)
k_nconv5t(const float* __restrict__ xin, const float* __restrict__ cin,
          float* __restrict__ xout, float* __restrict__ cout_,
          float* __restrict__ xds, float* __restrict__ cds,
          int H, int W, int bpr, int bpc){
    __shared__ __align__(16) float2 sm[CIN][SH5*SW5];
    __shared__ __align__(16) ull wpk2[2*CIN*25];
    __shared__ float wex[4];

    const int t = threadIdx.x;
    const int P = H*W;

    for(int i=t;i<2*CIN*25;i+=128) wpk2[i]=g_wd[WOFF+i];
    if(t<2){ wex[t]=g_ws[2*LYR+t]; wex[2+t]=g_ws[16+2*LYR+t]; }

    int bx = blockIdx.x % bpr;
    int tmp = blockIdx.x / bpr;
    int by = tmp % bpc;
    int b  = tmp / bpc;
    int gx0 = bx*TX5 - 2;
    int gy0 = by*TY5 - 2;

    const bool inter = (gx0>=0) && (gy0>=0) && (gx0+SW5<=W) && (gy0+SH5<=H);
    const int fx = t & 31, fy = t >> 5;

    #pragma unroll
    for(int ci=0;ci<CIN;ci++){
        const float* cb = cin + (size_t)(b*CIN+ci)*P;
        const float* xb = xin + (size_t)(b*CIN+ci)*P;
        if(inter){
            #pragma unroll
            for(int ly=fy; ly<SH5; ly+=4){
                const float* crow = cb + (size_t)(gy0+ly)*W + gx0;
                const float* xrow = xb + (size_t)(gy0+ly)*W + gx0;
                float2* srow = &sm[ci][ly*SW5];
                #pragma unroll
                for(int lx=fx; lx<SW5; lx+=32){
                    float c = crow[lx];
                    srow[lx] = make_float2(c, xrow[lx]*c);
                }
            }
        } else {
            #pragma unroll
            for(int ly=fy; ly<SH5; ly+=4){
                int gy = gy0+ly;
                float2* srow = &sm[ci][ly*SW5];
                #pragma unroll
                for(int lx=fx; lx<SW5; lx+=32){
                    int gx = gx0+lx;
                    float c=0.f, d=0.f;
                    if((unsigned)gx<(unsigned)W && (unsigned)gy<(unsigned)H){
                        int o = gy*W+gx;
                        c = cb[o]; d = xb[o]*c;
                    }
                    srow[lx] = make_float2(c, d);
                }
            }
        }
    }
    __syncthreads();

    const int tx = (t & 15)*4;
    const int ty = (t >> 4)*2;

    ull acc[2][2][4];
    #pragma unroll
    for(int a=0;a<2;a++)
      #pragma unroll
      for(int dy=0;dy<2;dy++)
        #pragma unroll
        for(int dx=0;dx<4;dx++) acc[a][dy][dx]=0ull;

    #pragma unroll
    for(int ci=0;ci<CIN;ci++){
        #pragma unroll
        for(int r=0;r<6;r++){
            ull v[8];
            const longlong2* p = (const longlong2*)&sm[ci][(ty+r)*SW5 + tx];
            #pragma unroll
            for(int j=0;j<4;j++){ longlong2 q=p[j]; v[2*j]=(ull)q.x; v[2*j+1]=(ull)q.y; }
            if(r<=4){   // dy=0, ky=r
                #pragma unroll
                for(int kx=0;kx<5;kx++){
                    longlong2 wp = *(const longlong2*)&wpk2[(ci*25 + r*5 + kx)*2];
                    ull wa=(ull)wp.x, wb=(ull)wp.y;
                    #pragma unroll
                    for(int dx=0;dx<4;dx++){
                        acc[0][0][dx]=fma2(wa, v[kx+dx], acc[0][0][dx]);
                        acc[1][0][dx]=fma2(wb, v[kx+dx], acc[1][0][dx]);
                    }
                }
            }
            if(r>=1){   // dy=1, ky=r-1
                #pragma unroll
                for(int kx=0;kx<5;kx++){
                    longlong2 wp = *(const longlong2*)&wpk2[(ci*25 + (r-1)*5 + kx)*2];
                    ull wa=(ull)wp.x, wb=(ull)wp.y;
                    #pragma unroll
                    for(int dx=0;dx<4;dx++){
                        acc[0][1][dx]=fma2(wa, v[kx+dx], acc[0][1][dx]);
                        acc[1][1][dx]=fma2(wb, v[kx+dx], acc[1][1][dx]);
                    }
                }
            }
        }
    }

    float rs0 = 1.0f/wex[0];
    float rs1 = 1.0f/wex[1];
    int gx = bx*TX5 + tx;
    int gyp = by*TY5 + ty;        // even; rows gyp, gyp+1
    if(gx < W && gyp < H){
        const int Wh = W>>1;
        const int Ph = Wh*(H>>1);
        #pragma unroll
        for(int a=0;a<2;a++){
            float rsa = a ? rs1 : rs0;
            float bia = wex[2+a];
            float rx[2][4], rc[2][4];
            #pragma unroll
            for(int dy=0;dy<2;dy++){
                #pragma unroll
                for(int j=0;j<2;j++){
                    float d0,n0,d1,n1;
                    unpack2(acc[a][dy][2*j],   d0, n0);
                    unpack2(acc[a][dy][2*j+1], d1, n1);
                    rx[dy][2*j]   = n0/(d0+EPSV)+bia;
                    rx[dy][2*j+1] = n1/(d1+EPSV)+bia;
                    rc[dy][2*j]   = d0*rsa;
                    rc[dy][2*j+1] = d1*rsa;
                }
                size_t o = (size_t)(b*2+a)*P + (size_t)(gyp+dy)*W + gx;
                *(float4*)&xout[o]  = make_float4(rx[dy][0],rx[dy][1],rx[dy][2],rx[dy][3]);
                *(float4*)&cout_[o] = make_float4(rc[dy][0],rc[dy][1],rc[dy][2],rc[dy][3]);
            }
            if(POOL){
                float2 pc, px;
                #pragma unroll
                for(int cell=0;cell<2;cell++){
                    int c0 = 2*cell;
                    float bc = rc[0][c0],  bxv = rx[0][c0];
                    if(rc[0][c0+1]>bc){ bc=rc[0][c0+1]; bxv=rx[0][c0+1]; }
                    if(rc[1][c0]  >bc){ bc=rc[1][c0];   bxv=rx[1][c0];   }
                    if(rc[1][c0+1]>bc){ bc=rc[1][c0+1]; bxv=rx[1][c0+1]; }
                    ((float*)&pc)[cell] = bc*0.25f;
                    ((float*)&px)[cell] = bxv;
                }
                size_t po = (size_t)(b*2+a)*Ph + (size_t)(gyp>>1)*Wh + (gx>>1);
                *(float2*)&cds[po] = pc;
                *(float2*)&xds[po] = px;
            }
        }
    }
}

// ---------------- tiled 3x3 cat nconv, smem weights, 4x2/thread ------------
#define TX3 64
#define TY3 16
#define SW3 (TX3+2)   // 66
#define SH3 (TY3+2)   // 18

template<bool UP_FIRST, int WOFF, int LYR>
__global__ void __launch_bounds__(128)
k_nconv3t(const float* __restrict__ xa, const float* __restrict__ ca,
          const float* __restrict__ xb, const float* __restrict__ cb,
          float* __restrict__ xout, float* __restrict__ cout_,
          int H, int W, int bpr, int bpc){
    __shared__ __align__(16) float2 sm[4][SH3*SW3];
    __shared__ __align__(16) ull wpk2[72];
    __shared__ float wex[4];

    const int t = threadIdx.x;
    const int P = H*W;
    const int Wh = W>>1, Ph = (W>>1)*(H>>1);

    for(int i=t;i<72;i+=128) wpk2[i]=g_wd[WOFF+i];
    if(t<2){ wex[t]=g_ws[2*LYR+t]; wex[2+t]=g_ws[16+2*LYR+t]; }

    int bx = blockIdx.x % bpr;
    int tmp = blockIdx.x / bpr;
    int by = tmp % bpc;
    int b  = tmp / bpc;
    int gx0 = bx*TX3 - 1;
    int gy0 = by*TY3 - 1;

    const bool inter = (gx0>=0) && (gy0>=0) && (gx0+SW3<=W) && (gy0+SH3<=H);
    const int fx = t & 31, fy = t >> 5;

    #pragma unroll
    for(int ci=0;ci<4;ci++){
        const bool fromUp = UP_FIRST ? (ci<2) : (ci>=2);
        const int ch = fromUp ? (UP_FIRST ? ci : ci-2) : (UP_FIRST ? ci-2 : ci);
        const float* cs = fromUp ? (cb + (size_t)(b*2+ch)*Ph) : (ca + (size_t)(b*2+ch)*P);
        const float* xs = fromUp ? (xb + (size_t)(b*2+ch)*Ph) : (xa + (size_t)(b*2+ch)*P);
        if(inter){
            #pragma unroll
            for(int ly=fy; ly<SH3; ly+=4){
                int gy = gy0+ly;
                float2* srow = &sm[ci][ly*SW3];
                if(fromUp){
                    const float* crow = cs + (size_t)(gy>>1)*Wh;
                    const float* xrow = xs + (size_t)(gy>>1)*Wh;
                    #pragma unroll
                    for(int lx=fx; lx<SW3; lx+=32){
                        int hx = (gx0+lx)>>1;
                        float c = crow[hx];
                        srow[lx] = make_float2(c, xrow[hx]*c);
                    }
                } else {
                    const float* crow = cs + (size_t)gy*W + gx0;
                    const float* xrow = xs + (size_t)gy*W + gx0;
                    #pragma unroll
                    for(int lx=fx; lx<SW3; lx+=32){
                        float c = crow[lx];
                        srow[lx] = make_float2(c, xrow[lx]*c);
                    }
                }
            }
        } else {
            #pragma unroll
            for(int ly=fy; ly<SH3; ly+=4){
                int gy = gy0+ly;
                float2* srow = &sm[ci][ly*SW3];
                #pragma unroll
                for(int lx=fx; lx<SW3; lx+=32){
                    int gx = gx0+lx;
                    float c=0.f, d=0.f;
                    if((unsigned)gx<(unsigned)W && (unsigned)gy<(unsigned)H){
                        int o = fromUp ? ((gy>>1)*Wh + (gx>>1)) : (gy*W+gx);
                        c = cs[o]; d = xs[o]*c;
                    }
                    srow[lx] = make_float2(c, d);
                }
            }
        }
    }
    __syncthreads();

    const int tx = (t & 15)*4;
    const int ty = (t >> 4)*2;

    ull acc[2][2][4];
    #pragma unroll
    for(int a=0;a<2;a++)
      #pragma unroll
      for(int dy=0;dy<2;dy++)
        #pragma unroll
        for(int dx=0;dx<4;dx++) acc[a][dy][dx]=0ull;

    #pragma unroll
    for(int ci=0;ci<4;ci++){
        #pragma unroll
        for(int r=0;r<4;r++){
            ull v[6];
            const longlong2* p = (const longlong2*)&sm[ci][(ty+r)*SW3 + tx];
            #pragma unroll
            for(int j=0;j<3;j++){ longlong2 q=p[j]; v[2*j]=(ull)q.x; v[2*j+1]=(ull)q.y; }
            if(r<=2){   // dy=0, ky=r
                #pragma unroll
                for(int kx=0;kx<3;kx++){
                    longlong2 wp = *(const longlong2*)&wpk2[(ci*9 + r*3 + kx)*2];
                    ull wa=(ull)wp.x, wb=(ull)wp.y;
                    #pragma unroll
                    for(int dx=0;dx<4;dx++){
                        acc[0][0][dx]=fma2(wa, v[kx+dx], acc[0][0][dx]);
                        acc[1][0][dx]=fma2(wb, v[kx+dx], acc[1][0][dx]);
                    }
                }
            }
            if(r>=1){   // dy=1, ky=r-1
                #pragma unroll
                for(int kx=0;kx<3;kx++){
                    longlong2 wp = *(const longlong2*)&wpk2[(ci*9 + (r-1)*3 + kx)*2];
                    ull wa=(ull)wp.x, wb=(ull)wp.y;
                    #pragma unroll
                    for(int dx=0;dx<4;dx++){
                        acc[0][1][dx]=fma2(wa, v[kx+dx], acc[0][1][dx]);
                        acc[1][1][dx]=fma2(wb, v[kx+dx], acc[1][1][dx]);
                    }
                }
            }
        }
    }

    float rs0 = 1.0f/wex[0];
    float rs1 = 1.0f/wex[1];
    float bi0 = wex[2];
    float bi1 = wex[3];
    int gx = bx*TX3 + tx;
    if(gx < W){
        #pragma unroll
        for(int dy=0;dy<2;dy++){
            int gy = by*TY3 + ty + dy;
            if(gy>=H) continue;
            #pragma unroll
            for(int a=0;a<2;a++){
                float d0,n0,d1,n1,d2,n2,d3,n3;
                unpack2(acc[a][dy][0], d0, n0);
                unpack2(acc[a][dy][1], d1, n1);
                unpack2(acc[a][dy][2], d2, n2);
                unpack2(acc[a][dy][3], d3, n3);
                float bia = a ? bi1 : bi0;
                float rsa = a ? rs1 : rs0;
                float4 xo = make_float4(n0/(d0+EPSV)+bia, n1/(d1+EPSV)+bia,
                                        n2/(d2+EPSV)+bia, n3/(d3+EPSV)+bia);
                float4 co = make_float4(d0*rsa, d1*rsa, d2*rsa, d3*rsa);
                size_t o = (size_t)(b*2+a)*P + (size_t)gy*W + gx;
                *(float4*)&xout[o]  = xo;
                *(float4*)&cout_[o] = co;
            }
        }
    }
}

// final 1x1 nconv, float4-vectorized
__global__ void k_nconv1x1(const float* __restrict__ xin, const float* __restrict__ cin,
                           float* __restrict__ xout, float* __restrict__ cout_){
    int idx = blockIdx.x*blockDim.x + threadIdx.x;
    const int Q = P0/4;
    if(idx >= BB*Q) return;
    int q = idx % Q;
    int b = idx / Q;
    const float4* x0p = (const float4*)(xin + (size_t)(b*2+0)*P0) + q;
    const float4* x1p = (const float4*)(xin + (size_t)(b*2+1)*P0) + q;
    const float4* c0p = (const float4*)(cin + (size_t)(b*2+0)*P0) + q;
    const float4* c1p = (const float4*)(cin + (size_t)(b*2+1)*P0) + q;
    float4 X0=*x0p, X1=*x1p, C0=*c0p, C1=*c1p;
    float w0,w1,hi;
    unpack2(g_wd[466], w0, hi);
    unpack2(g_wd[468], w1, hi);
    float rsum = 1.0f/g_ws[12];
    float bi = g_ws[28];
    float4 XO, CO;
    #pragma unroll
    for(int k=0;k<4;k++){
        float c0v = ((const float*)&C0)[k];
        float c1v = ((const float*)&C1)[k];
        float den = w0*c0v + w1*c1v;
        float nom = w0*(((const float*)&X0)[k]*c0v) + w1*(((const float*)&X1)[k]*c1v);
        ((float*)&XO)[k] = nom/(den+EPSV) + bi;
        ((float*)&CO)[k] = den*rsum;
    }
    ((float4*)(xout  + (size_t)b*P0))[q] = XO;
    ((float4*)(cout_ + (size_t)b*P0))[q] = CO;
}

extern "C" void kernel_launch(void* const* d_in, const int* in_sizes, int n_in,
                              void* d_out, int out_size){
    const float* x0 = (const float*)d_in[0];
    const float* c0 = (const float*)d_in[1];
    const float* w1 = (const float*)d_in[2];  const float* b1 = (const float*)d_in[3];
    const float* w2 = (const float*)d_in[4];  const float* b2 = (const float*)d_in[5];
    const float* w3 = (const float*)d_in[6];  const float* b3 = (const float*)d_in[7];
    const float* w4 = (const float*)d_in[8];  const float* b4 = (const float*)d_in[9];
    const float* w5 = (const float*)d_in[10]; const float* b5 = (const float*)d_in[11];
    const float* w6 = (const float*)d_in[12]; const float* b6 = (const float*)d_in[13];
    const float* w7 = (const float*)d_in[14]; const float* b7 = (const float*)d_in[15];

    float* S = nullptr;  cudaGetSymbolAddress((void**)&S,  g_scratch);

    float *xA=S,   *cA=S+N0,   *xB=S+2*N0, *cB=S+3*N0, *x1=S+4*N0, *c1=S+5*N0;
    float *Sh = S + 6*N0;
    float *xha=Sh, *cha=Sh+N1, *xhb=Sh+2*N1, *chb=Sh+3*N1, *x2d=Sh+4*N1, *c2d=Sh+5*N1;
    float *Sq = Sh + 6*N1;
    float *xq=Sq,  *cq=Sq+N2,  *x3d=Sq+2*N2, *c3d=Sq+3*N2, *x34=Sq+4*N2, *c34=Sq+5*N2;
    float *Se = Sq + 6*N2;
    float *xe=Se,  *ce=Se+N3,  *x4=Se+2*N3,  *c4=Se+3*N3;

    auto tiles = [&](int H, int W, int &bpr, int &bpc)->int{
        bpr = (W + TX5 - 1)/TX5; bpc = (H + TY5 - 1)/TY5;
        return bpr*bpc*BB;
    };

    k_prep<<<1,128>>>(w1,b1,w2,b2,w3,b3,w4,b4,w5,b5,w6,b6,w7,b7);

    int bpr, bpc, g;

    // encoder full res (3rd layer fuses pool -> level-1 inputs)
    g = tiles(H0,W0,bpr,bpc);
    k_nconv5t<1,0,0,false>  <<<g,128>>>(x0, c0, xA, cA, nullptr, nullptr, H0, W0, bpr, bpc);
    k_nconv5t<2,50,1,false> <<<g,128>>>(xA, cA, xB, cB, nullptr, nullptr, H0, W0, bpr, bpc);
    k_nconv5t<2,150,2,true> <<<g,128>>>(xB, cB, x1, c1, xha, cha, H0, W0, bpr, bpc);

    // level 1 (2nd layer fuses pool -> level-2 inputs)
    g = tiles(H1,W1,bpr,bpc);
    k_nconv5t<2,50,1,false> <<<g,128>>>(xha, cha, xhb, chb, nullptr, nullptr, H1, W1, bpr, bpc);
    k_nconv5t<2,150,2,true> <<<g,128>>>(xhb, chb, x2d, c2d, xq, cq, H1, W1, bpr, bpc);

    // level 2 (fuses pool -> level-3 inputs)
    g = tiles(H2,W2,bpr,bpc);
    k_nconv5t<2,50,1,true>  <<<g,128>>>(xq, cq, x3d, c3d, xe, ce, H2, W2, bpr, bpc);

    // level 3
    g = tiles(H3,W3,bpr,bpc);
    k_nconv5t<2,50,1,false> <<<g,128>>>(xe, ce, x4, c4, nullptr, nullptr, H3, W3, bpr, bpc);

    // decoder
    g = tiles(H2,W2,bpr,bpc);
    k_nconv3t<false,250,3><<<g,128>>>(x3d, c3d, x4, c4,   x34, c34, H2, W2, bpr, bpc);
    g = tiles(H1,W1,bpr,bpc);
    k_nconv3t<false,322,4><<<g,128>>>(x2d, c2d, x34, c34, xha, cha, H1, W1, bpr, bpc);
    g = tiles(H0,W0,bpr,bpc);
    k_nconv3t<true,394,5> <<<g,128>>>(x1, c1, xha, cha,   xA, cA, H0, W0, bpr, bpc);

    float* out = (float*)d_out;
    k_nconv1x1<<<(BB*(P0/4)+255)/256,256>>>(xA, cA, out, out + (size_t)BB*P0);
}

// round 9
// speedup vs baseline: 1.5162x; 1.0273x over previous
#include <cuda_runtime.h>
#include <math.h>

#define EPSV 1e-20f

#define BB 16
#define H0 352
#define W0 1216
#define H1 176
#define W1 608
#define H2 88
#define W2 304
#define H3 44
#define W3 152

#define P0 (H0*W0)
#define P1 (H1*W1)
#define P2 (H2*W2)
#define P3 (H3*W3)

// float2 element counts per interleaved (c, x*c) tensor
#define M0 ((size_t)BB*2*P0)
#define M1 ((size_t)BB*2*P1)
#define M2 ((size_t)BB*2*P2)
#define M3 ((size_t)BB*2*P3)

typedef unsigned long long ull;

// 3 full-res + 3 L1 + 3 L2 + 2 L3 interleaved tensors
__device__ __align__(16) float2 g_scratch[3*M0 + 3*M1 + 3*M2 + 2*M3];
__device__ ull   g_wd[480];
__device__ float g_ws[32];

// dup-pair weight layout (ull units):
// w1:0(50) w2:50(100) w3:150(100) w4:250(72) w5:322(72) w6:394(72) w7:466(4)
// entry: OFF + (ci*K + k)*2 + cout
// g_ws: sums at [2*lyr + co], biases at [16 + 2*lyr + co]

__device__ __forceinline__ ull fma2(ull a, ull b, ull c){
    ull d; asm("fma.rn.f32x2 %0, %1, %2, %3;" : "=l"(d) : "l"(a), "l"(b), "l"(c)); return d;
}
__device__ __forceinline__ void unpack2(ull v, float &a, float &b){
    asm("mov.b64 {%0,%1}, %2;" : "=f"(a), "=f"(b) : "l"(v));
}
__device__ __forceinline__ ull dupf(float w){
    float2 f2 = make_float2(w, w);
    return *(ull*)&f2;
}
__device__ __forceinline__ float sp10(float p){
    float z = 10.0f * p;
    float r = (z > 20.0f) ? z : log1pf(expf(z));
    return r * 0.1f;
}

__global__ void k_prep(const float* __restrict__ w1, const float* __restrict__ b1,
                       const float* __restrict__ w2, const float* __restrict__ b2,
                       const float* __restrict__ w3, const float* __restrict__ b3,
                       const float* __restrict__ w4, const float* __restrict__ b4,
                       const float* __restrict__ w5, const float* __restrict__ b5,
                       const float* __restrict__ w6, const float* __restrict__ b6,
                       const float* __restrict__ w7, const float* __restrict__ b7){
    const float* wp[7]={w1,w2,w3,w4,w5,w6,w7};
    const float* bp[7]={b1,b2,b3,b4,b5,b6,b7};
    const int cin[7]={1,2,2,4,4,4,2};
    const int kk [7]={25,25,25,9,9,9,1};
    const int co [7]={2,2,2,2,2,2,1};
    const int off[7]={0,50,150,250,322,394,466};
    int t=threadIdx.x;
    for(int l=0;l<7;l++){
        int n=cin[l]*kk[l];
        int tot=n*co[l];
        for(int i=t;i<tot;i+=blockDim.x){
            int c=i/n, e=i%n;
            g_wd[off[l]+e*2+c]=dupf(sp10(wp[l][c*n+e]));
        }
    }
    __syncthreads();
    if(t==0){
        for(int l=0;l<7;l++){
            int n=cin[l]*kk[l];
            for(int c=0;c<co[l];c++){
                float s=0.f;
                for(int e=0;e<n;e++){ float lo,hi; unpack2(g_wd[off[l]+e*2+c],lo,hi); s+=lo; }
                g_ws[2*l+c]=s;
                g_ws[16+2*l+c]=bp[l][c];
            }
        }
    }
}

// ---------------- tiled 5x5 nconv, interleaved I/O, opt. fused pool --------
#define TX5 64
#define TY5 16
#define SW5 (TX5+4)   // 68
#define SH5 (TY5+4)   // 20

template<int CIN, int WOFF, int LYR, bool POOL, bool SPLIT_IN>
__global__ void __launch_bounds__(128,7)
k_nconv5t(const float2* __restrict__ in, const float* __restrict__ xs, const float* __restrict__ cs,
          float2* __restrict__ out, float2* __restrict__ outds,
          int H, int W, int bpr, int bpc){
    __shared__ __align__(16) float2 sm[CIN][SH5*SW5];
    __shared__ __align__(16) ull wpk2[2*CIN*25];
    __shared__ float wex[4];

    const int t = threadIdx.x;
    const int P = H*W;

    for(int i=t;i<2*CIN*25;i+=128) wpk2[i]=g_wd[WOFF+i];
    if(t<2){ wex[t]=g_ws[2*LYR+t]; wex[2+t]=g_ws[16+2*LYR+t]; }

    int bx = blockIdx.x % bpr;
    int tmp = blockIdx.x / bpr;
    int by = tmp % bpc;
    int b  = tmp / bpc;
    int gx0 = bx*TX5 - 2;   // always even
    int gy0 = by*TY5 - 2;

    const bool inter = (gx0>=0) && (gy0>=0) && (gx0+SW5<=W) && (gy0+SH5<=H);
    const int fx = t & 31, fy = t >> 5;

    #pragma unroll
    for(int ci=0;ci<CIN;ci++){
        if(!SPLIT_IN){
            const float2* src = in + (size_t)(b*CIN+ci)*P;
            if(inter){
                #pragma unroll
                for(int ly=fy; ly<SH5; ly+=4){
                    const float4* grow = (const float4*)(src + (size_t)(gy0+ly)*W + gx0);
                    float4* srow = (float4*)&sm[ci][ly*SW5];
                    #pragma unroll
                    for(int j=fx; j<SW5/2; j+=32) srow[j] = grow[j];
                }
            } else {
                #pragma unroll
                for(int ly=fy; ly<SH5; ly+=4){
                    int gy = gy0+ly;
                    float2* srow = &sm[ci][ly*SW5];
                    #pragma unroll
                    for(int lx=fx; lx<SW5; lx+=32){
                        int gx = gx0+lx;
                        float2 v = make_float2(0.f, 0.f);
                        if((unsigned)gx<(unsigned)W && (unsigned)gy<(unsigned)H)
                            v = src[(size_t)gy*W+gx];
                        srow[lx] = v;
                    }
                }
            }
        } else {
            const float* cb = cs + (size_t)(b*CIN+ci)*P;
            const float* xb = xs + (size_t)(b*CIN+ci)*P;
            if(inter){
                #pragma unroll
                for(int ly=fy; ly<SH5; ly+=4){
                    const float* crow = cb + (size_t)(gy0+ly)*W + gx0;
                    const float* xrow = xb + (size_t)(gy0+ly)*W + gx0;
                    float2* srow = &sm[ci][ly*SW5];
                    #pragma unroll
                    for(int lx=fx; lx<SW5; lx+=32){
                        float c = crow[lx];
                        srow[lx] = make_float2(c, xrow[lx]*c);
                    }
                }
            } else {
                #pragma unroll
                for(int ly=fy; ly<SH5; ly+=4){
                    int gy = gy0+ly;
                    float2* srow = &sm[ci][ly*SW5];
                    #pragma unroll
                    for(int lx=fx; lx<SW5; lx+=32){
                        int gx = gx0+lx;
                        float c=0.f, d=0.f;
                        if((unsigned)gx<(unsigned)W && (unsigned)gy<(unsigned)H){
                            int o = gy*W+gx;
                            c = cb[o]; d = xb[o]*c;
                        }
                        srow[lx] = make_float2(c, d);
                    }
                }
            }
        }
    }
    __syncthreads();

    const int tx = (t & 15)*4;
    const int ty = (t >> 4)*2;

    ull acc[2][2][4];
    #pragma unroll
    for(int a=0;a<2;a++)
      #pragma unroll
      for(int dy=0;dy<2;dy++)
        #pragma unroll
        for(int dx=0;dx<4;dx++) acc[a][dy][dx]=0ull;

    #pragma unroll
    for(int ci=0;ci<CIN;ci++){
        #pragma unroll
        for(int r=0;r<6;r++){
            ull v[8];
            const longlong2* p = (const longlong2*)&sm[ci][(ty+r)*SW5 + tx];
            #pragma unroll
            for(int j=0;j<4;j++){ longlong2 q=p[j]; v[2*j]=(ull)q.x; v[2*j+1]=(ull)q.y; }
            if(r<=4){   // dy=0, ky=r
                #pragma unroll
                for(int kx=0;kx<5;kx++){
                    longlong2 wp = *(const longlong2*)&wpk2[(ci*25 + r*5 + kx)*2];
                    ull wa=(ull)wp.x, wb=(ull)wp.y;
                    #pragma unroll
                    for(int dx=0;dx<4;dx++){
                        acc[0][0][dx]=fma2(wa, v[kx+dx], acc[0][0][dx]);
                        acc[1][0][dx]=fma2(wb, v[kx+dx], acc[1][0][dx]);
                    }
                }
            }
            if(r>=1){   // dy=1, ky=r-1
                #pragma unroll
                for(int kx=0;kx<5;kx++){
                    longlong2 wp = *(const longlong2*)&wpk2[(ci*25 + (r-1)*5 + kx)*2];
                    ull wa=(ull)wp.x, wb=(ull)wp.y;
                    #pragma unroll
                    for(int dx=0;dx<4;dx++){
                        acc[0][1][dx]=fma2(wa, v[kx+dx], acc[0][1][dx]);
                        acc[1][1][dx]=fma2(wb, v[kx+dx], acc[1][1][dx]);
                    }
                }
            }
        }
    }

    float rs0 = 1.0f/wex[0];
    float rs1 = 1.0f/wex[1];
    int gx = bx*TX5 + tx;
    int gyp = by*TY5 + ty;        // even; rows gyp, gyp+1
    if(gx < W && gyp < H){
        const int Wh = W>>1;
        const int Ph = Wh*(H>>1);
        #pragma unroll
        for(int a=0;a<2;a++){
            float rsa = a ? rs1 : rs0;
            float bia = wex[2+a];
            float rx[2][4], rc[2][4];
            #pragma unroll
            for(int dy=0;dy<2;dy++){
                #pragma unroll
                for(int j=0;j<2;j++){
                    float d0,n0,d1,n1;
                    unpack2(acc[a][dy][2*j],   d0, n0);
                    unpack2(acc[a][dy][2*j+1], d1, n1);
                    rx[dy][2*j]   = n0/(d0+EPSV)+bia;
                    rx[dy][2*j+1] = n1/(d1+EPSV)+bia;
                    rc[dy][2*j]   = d0*rsa;
                    rc[dy][2*j+1] = d1*rsa;
                }
                float4* dst = (float4*)(out + (size_t)(b*2+a)*P + (size_t)(gyp+dy)*W + gx);
                dst[0] = make_float4(rc[dy][0], rx[dy][0]*rc[dy][0],
                                     rc[dy][1], rx[dy][1]*rc[dy][1]);
                dst[1] = make_float4(rc[dy][2], rx[dy][2]*rc[dy][2],
                                     rc[dy][3], rx[dy][3]*rc[dy][3]);
            }
            if(POOL){
                float pc[2], px[2];
                #pragma unroll
                for(int cell=0;cell<2;cell++){
                    int c0 = 2*cell;
                    float bc = rc[0][c0],  bxv = rx[0][c0];
                    if(rc[0][c0+1]>bc){ bc=rc[0][c0+1]; bxv=rx[0][c0+1]; }
                    if(rc[1][c0]  >bc){ bc=rc[1][c0];   bxv=rx[1][c0];   }
                    if(rc[1][c0+1]>bc){ bc=rc[1][c0+1]; bxv=rx[1][c0+1]; }
                    pc[cell] = bc*0.25f;
                    px[cell] = bxv;
                }
                float4* pdst = (float4*)(outds + (size_t)(b*2+a)*Ph + (size_t)(gyp>>1)*Wh + (gx>>1));
                pdst[0] = make_float4(pc[0], px[0]*pc[0], pc[1], px[1]*pc[1]);
            }
        }
    }
}

// ---------------- tiled 3x3 cat nconv, interleaved I/O ---------------------
#define TX3 64
#define TY3 16
#define SW3 (TX3+2)   // 66
#define SH3 (TY3+2)   // 18

template<bool UP_FIRST, int WOFF, int LYR>
__global__ void __launch_bounds__(128)
k_nconv3t(const float2* __restrict__ na, const float2* __restrict__ ub,
          float2* __restrict__ out,
          int H, int W, int bpr, int bpc){
    __shared__ __align__(16) float2 sm[4][SH3*SW3];
    __shared__ __align__(16) ull wpk2[72];
    __shared__ float wex[4];

    const int t = threadIdx.x;
    const int P = H*W;
    const int Wh = W>>1, Ph = (W>>1)*(H>>1);

    for(int i=t;i<72;i+=128) wpk2[i]=g_wd[WOFF+i];
    if(t<2){ wex[t]=g_ws[2*LYR+t]; wex[2+t]=g_ws[16+2*LYR+t]; }

    int bx = blockIdx.x % bpr;
    int tmp = blockIdx.x / bpr;
    int by = tmp % bpc;
    int b  = tmp / bpc;
    int gx0 = bx*TX3 - 1;
    int gy0 = by*TY3 - 1;

    const bool inter = (gx0>=0) && (gy0>=0) && (gx0+SW3<=W) && (gy0+SH3<=H);
    const int fx = t & 31, fy = t >> 5;

    #pragma unroll
    for(int ci=0;ci<4;ci++){
        const bool fromUp = UP_FIRST ? (ci<2) : (ci>=2);
        const int ch = fromUp ? (UP_FIRST ? ci : ci-2) : (UP_FIRST ? ci-2 : ci);
        const float2* src = fromUp ? (ub + (size_t)(b*2+ch)*Ph) : (na + (size_t)(b*2+ch)*P);
        if(inter){
            #pragma unroll
            for(int ly=fy; ly<SH3; ly+=4){
                int gy = gy0+ly;
                float2* srow = &sm[ci][ly*SW3];
                if(fromUp){
                    const float2* grow = src + (size_t)(gy>>1)*Wh;
                    #pragma unroll
                    for(int lx=fx; lx<SW3; lx+=32)
                        srow[lx] = grow[(gx0+lx)>>1];
                } else {
                    const float2* grow = src + (size_t)gy*W + gx0;
                    #pragma unroll
                    for(int lx=fx; lx<SW3; lx+=32)
                        srow[lx] = grow[lx];
                }
            }
        } else {
            #pragma unroll
            for(int ly=fy; ly<SH3; ly+=4){
                int gy = gy0+ly;
                float2* srow = &sm[ci][ly*SW3];
                #pragma unroll
                for(int lx=fx; lx<SW3; lx+=32){
                    int gx = gx0+lx;
                    float2 v = make_float2(0.f, 0.f);
                    if((unsigned)gx<(unsigned)W && (unsigned)gy<(unsigned)H)
                        v = fromUp ? src[(size_t)(gy>>1)*Wh + (gx>>1)]
                                   : src[(size_t)gy*W + gx];
                    srow[lx] = v;
                }
            }
        }
    }
    __syncthreads();

    const int tx = (t & 15)*4;
    const int ty = (t >> 4)*2;

    ull acc[2][2][4];
    #pragma unroll
    for(int a=0;a<2;a++)
      #pragma unroll
      for(int dy=0;dy<2;dy++)
        #pragma unroll
        for(int dx=0;dx<4;dx++) acc[a][dy][dx]=0ull;

    #pragma unroll
    for(int ci=0;ci<4;ci++){
        #pragma unroll
        for(int r=0;r<4;r++){
            ull v[6];
            const longlong2* p = (const longlong2*)&sm[ci][(ty+r)*SW3 + tx];
            #pragma unroll
            for(int j=0;j<3;j++){ longlong2 q=p[j]; v[2*j]=(ull)q.x; v[2*j+1]=(ull)q.y; }
            if(r<=2){   // dy=0, ky=r
                #pragma unroll
                for(int kx=0;kx<3;kx++){
                    longlong2 wp = *(const longlong2*)&wpk2[(ci*9 + r*3 + kx)*2];
                    ull wa=(ull)wp.x, wb=(ull)wp.y;
                    #pragma unroll
                    for(int dx=0;dx<4;dx++){
                        acc[0][0][dx]=fma2(wa, v[kx+dx], acc[0][0][dx]);
                        acc[1][0][dx]=fma2(wb, v[kx+dx], acc[1][0][dx]);
                    }
                }
            }
            if(r>=1){   // dy=1, ky=r-1
                #pragma unroll
                for(int kx=0;kx<3;kx++){
                    longlong2 wp = *(const longlong2*)&wpk2[(ci*9 + (r-1)*3 + kx)*2];
                    ull wa=(ull)wp.x, wb=(ull)wp.y;
                    #pragma unroll
                    for(int dx=0;dx<4;dx++){
                        acc[0][1][dx]=fma2(wa, v[kx+dx], acc[0][1][dx]);
                        acc[1][1][dx]=fma2(wb, v[kx+dx], acc[1][1][dx]);
                    }
                }
            }
        }
    }

    float rs0 = 1.0f/wex[0];
    float rs1 = 1.0f/wex[1];
    float bi0 = wex[2];
    float bi1 = wex[3];
    int gx = bx*TX3 + tx;
    if(gx < W){
        #pragma unroll
        for(int dy=0;dy<2;dy++){
            int gy = by*TY3 + ty + dy;
            if(gy>=H) continue;
            #pragma unroll
            for(int a=0;a<2;a++){
                float d0,n0,d1,n1,d2,n2,d3,n3;
                unpack2(acc[a][dy][0], d0, n0);
                unpack2(acc[a][dy][1], d1, n1);
                unpack2(acc[a][dy][2], d2, n2);
                unpack2(acc[a][dy][3], d3, n3);
                float bia = a ? bi1 : bi0;
                float rsa = a ? rs1 : rs0;
                float x0v = n0/(d0+EPSV)+bia, x1v = n1/(d1+EPSV)+bia;
                float x2v = n2/(d2+EPSV)+bia, x3v = n3/(d3+EPSV)+bia;
                float c0v = d0*rsa, c1v = d1*rsa, c2v = d2*rsa, c3v = d3*rsa;
                float4* dst = (float4*)(out + (size_t)(b*2+a)*P + (size_t)gy*W + gx);
                dst[0] = make_float4(c0v, x0v*c0v, c1v, x1v*c1v);
                dst[1] = make_float4(c2v, x2v*c2v, c3v, x3v*c3v);
            }
        }
    }
}

// final 1x1 nconv: interleaved in, plain planes out
__global__ void k_nconv1x1(const float2* __restrict__ in,
                           float* __restrict__ xout, float* __restrict__ cout_){
    int idx = blockIdx.x*blockDim.x + threadIdx.x;
    const int Q = P0/4;
    if(idx >= BB*Q) return;
    int q = idx % Q;
    int b = idx / Q;
    const float4* p0 = (const float4*)(in + (size_t)(b*2+0)*P0) + 2*q;
    const float4* p1 = (const float4*)(in + (size_t)(b*2+1)*P0) + 2*q;
    float4 u0 = p0[0], u1 = p0[1];
    float4 v0 = p1[0], v1 = p1[1];
    float w0,w1,hi;
    unpack2(g_wd[466], w0, hi);
    unpack2(g_wd[468], w1, hi);
    float rsum = 1.0f/g_ws[12];
    float bi = g_ws[28];
    float c0[4] = {u0.x, u0.z, u1.x, u1.z};
    float d0[4] = {u0.y, u0.w, u1.y, u1.w};
    float c1[4] = {v0.x, v0.z, v1.x, v1.z};
    float d1[4] = {v0.y, v0.w, v1.y, v1.w};
    float4 XO, CO;
    #pragma unroll
    for(int k=0;k<4;k++){
        float den = w0*c0[k] + w1*c1[k];
        float nom = w0*d0[k] + w1*d1[k];
        ((float*)&XO)[k] = nom/(den+EPSV) + bi;
        ((float*)&CO)[k] = den*rsum;
    }
    ((float4*)(xout  + (size_t)b*P0))[q] = XO;
    ((float4*)(cout_ + (size_t)b*P0))[q] = CO;
}

extern "C" void kernel_launch(void* const* d_in, const int* in_sizes, int n_in,
                              void* d_out, int out_size){
    const float* x0 = (const float*)d_in[0];
    const float* c0 = (const float*)d_in[1];
    const float* w1 = (const float*)d_in[2];  const float* b1 = (const float*)d_in[3];
    const float* w2 = (const float*)d_in[4];  const float* b2 = (const float*)d_in[5];
    const float* w3 = (const float*)d_in[6];  const float* b3 = (const float*)d_in[7];
    const float* w4 = (const float*)d_in[8];  const float* b4 = (const float*)d_in[9];
    const float* w5 = (const float*)d_in[10]; const float* b5 = (const float*)d_in[11];
    const float* w6 = (const float*)d_in[12]; const float* b6 = (const float*)d_in[13];
    const float* w7 = (const float*)d_in[14]; const float* b7 = (const float*)d_in[15];

    float2* S = nullptr;  cudaGetSymbolAddress((void**)&S,  g_scratch);

    float2 *A  = S,        *Bv = S + M0,     *T1 = S + 2*M0;
    float2 *HA = S + 3*M0, *HB = HA + M1,    *T2 = HA + 2*M1;
    float2 *Q  = HA + 3*M1,*T3 = Q + M2,     *T34= Q + 2*M2;
    float2 *E  = Q + 3*M2, *T4 = E + M3;

    auto tiles = [&](int H, int W, int &bpr, int &bpc)->int{
        bpr = (W + TX5 - 1)/TX5; bpc = (H + TY5 - 1)/TY5;
        return bpr*bpc*BB;
    };

    k_prep<<<1,128>>>(w1,b1,w2,b2,w3,b3,w4,b4,w5,b5,w6,b6,w7,b7);

    int bpr, bpc, g;

    // encoder full res (3rd layer fuses pool -> level-1 inputs)
    g = tiles(H0,W0,bpr,bpc);
    k_nconv5t<1,0,0,false,true>   <<<g,128>>>(nullptr, x0, c0, A, nullptr, H0, W0, bpr, bpc);
    k_nconv5t<2,50,1,false,false> <<<g,128>>>(A, nullptr, nullptr, Bv, nullptr, H0, W0, bpr, bpc);
    k_nconv5t<2,150,2,true,false> <<<g,128>>>(Bv, nullptr, nullptr, T1, HA, H0, W0, bpr, bpc);

    // level 1 (2nd layer fuses pool -> level-2 inputs)
    g = tiles(H1,W1,bpr,bpc);
    k_nconv5t<2,50,1,false,false> <<<g,128>>>(HA, nullptr, nullptr, HB, nullptr, H1, W1, bpr, bpc);
    k_nconv5t<2,150,2,true,false> <<<g,128>>>(HB, nullptr, nullptr, T2, Q, H1, W1, bpr, bpc);

    // level 2 (fuses pool -> level-3 inputs)
    g = tiles(H2,W2,bpr,bpc);
    k_nconv5t<2,50,1,true,false>  <<<g,128>>>(Q, nullptr, nullptr, T3, E, H2, W2, bpr, bpc);

    // level 3
    g = tiles(H3,W3,bpr,bpc);
    k_nconv5t<2,50,1,false,false> <<<g,128>>>(E, nullptr, nullptr, T4, nullptr, H3, W3, bpr, bpc);

    // decoder
    g = tiles(H2,W2,bpr,bpc);
    k_nconv3t<false,250,3><<<g,128>>>(T3, T4,  T34, H2, W2, bpr, bpc);
    g = tiles(H1,W1,bpr,bpc);
    k_nconv3t<false,322,4><<<g,128>>>(T2, T34, HA,  H1, W1, bpr, bpc);
    g = tiles(H0,W0,bpr,bpc);
    k_nconv3t<true,394,5> <<<g,128>>>(T1, HA,  A,   H0, W0, bpr, bpc);

    float* out = (float*)d_out;
    k_nconv1x1<<<(BB*(P0/4)+255)/256,256>>>(A, out, out + (size_t)BB*P0);
}

// round 10
// speedup vs baseline: 1.5414x; 1.0167x over previous
#include <cuda_runtime.h>
#include <math.h>

#define EPSV 1e-20f

#define BB 16
#define H0 352
#define W0 1216
#define H1 176
#define W1 608
#define H2 88
#define W2 304
#define H3 44
#define W3 152

#define P0 (H0*W0)
#define P1 (H1*W1)
#define P2 (H2*W2)
#define P3 (H3*W3)

// float2 element counts per interleaved (c, x*c) tensor
#define M0 ((size_t)BB*2*P0)
#define M1 ((size_t)BB*2*P1)
#define M2 ((size_t)BB*2*P2)
#define M3 ((size_t)BB*2*P3)

typedef unsigned long long ull;

__device__ __align__(16) float2 g_scratch[3*M0 + 3*M1 + 3*M2 + 2*M3];
__device__ ull   g_wd[480];
__device__ float g_ws[32];

// dup-pair weight layout (ull units):
// w1:0(50) w2:50(100) w3:150(100) w4:250(72) w5:322(72) w6:394(72) w7:466(4)
// entry: OFF + (ci*K + k)*2 + cout
// g_ws: sums at [2*lyr + co], biases at [16 + 2*lyr + co]

__device__ __forceinline__ ull fma2(ull a, ull b, ull c){
    ull d; asm("fma.rn.f32x2 %0, %1, %2, %3;" : "=l"(d) : "l"(a), "l"(b), "l"(c)); return d;
}
__device__ __forceinline__ void unpack2(ull v, float &a, float &b){
    asm("mov.b64 {%0,%1}, %2;" : "=f"(a), "=f"(b) : "l"(v));
}
__device__ __forceinline__ ull dupf(float w){
    float2 f2 = make_float2(w, w);
    return *(ull*)&f2;
}
__device__ __forceinline__ float sp10(float p){
    float z = 10.0f * p;
    float r = (z > 20.0f) ? z : log1pf(expf(z));
    return r * 0.1f;
}

__global__ void k_prep(const float* __restrict__ w1, const float* __restrict__ b1,
                       const float* __restrict__ w2, const float* __restrict__ b2,
                       const float* __restrict__ w3, const float* __restrict__ b3,
                       const float* __restrict__ w4, const float* __restrict__ b4,
                       const float* __restrict__ w5, const float* __restrict__ b5,
                       const float* __restrict__ w6, const float* __restrict__ b6,
                       const float* __restrict__ w7, const float* __restrict__ b7){
    const float* wp[7]={w1,w2,w3,w4,w5,w6,w7};
    const float* bp[7]={b1,b2,b3,b4,b5,b6,b7};
    const int cin[7]={1,2,2,4,4,4,2};
    const int kk [7]={25,25,25,9,9,9,1};
    const int co [7]={2,2,2,2,2,2,1};
    const int off[7]={0,50,150,250,322,394,466};
    int t=threadIdx.x;
    for(int l=0;l<7;l++){
        int n=cin[l]*kk[l];
        int tot=n*co[l];
        for(int i=t;i<tot;i+=blockDim.x){
            int c=i/n, e=i%n;
            g_wd[off[l]+e*2+c]=dupf(sp10(wp[l][c*n+e]));
        }
    }
    __syncthreads();
    if(t==0){
        for(int l=0;l<7;l++){
            int n=cin[l]*kk[l];
            for(int c=0;c<co[l];c++){
                float s=0.f;
                for(int e=0;e<n;e++){ float lo,hi; unpack2(g_wd[off[l]+e*2+c],lo,hi); s+=lo; }
                g_ws[2*l+c]=s;
                g_ws[16+2*l+c]=bp[l][c];
            }
        }
    }
}

// ---------------- tiled 5x5 nconv, interleaved I/O, opt. fused pool --------
#define TX5 64
#define TY5 16
#define SW5 (TX5+4)   // 68
#define SH5 (TY5+4)   // 20

template<int CIN, int WOFF, int LYR, bool POOL, bool SPLIT_IN>
__global__ void __launch_bounds__(128,6)
k_nconv5t(const float2* __restrict__ in, const float* __restrict__ xs, const float* __restrict__ cs,
          float2* __restrict__ out, float2* __restrict__ outds,
          int H, int W, int bpr, int bpc){
    __shared__ __align__(16) float2 sm[CIN][SH5*SW5];
    __shared__ __align__(16) ull wpk2[2*CIN*25];
    __shared__ float wex[4];

    const int t = threadIdx.x;
    const int P = H*W;

    for(int i=t;i<2*CIN*25;i+=128) wpk2[i]=g_wd[WOFF+i];
    if(t<2){ wex[t]=g_ws[2*LYR+t]; wex[2+t]=g_ws[16+2*LYR+t]; }

    int bx = blockIdx.x % bpr;
    int tmp = blockIdx.x / bpr;
    int by = tmp % bpc;
    int b  = tmp / bpc;
    int gx0 = bx*TX5 - 2;   // always even
    int gy0 = by*TY5 - 2;

    const bool inter = (gx0>=0) && (gy0>=0) && (gx0+SW5<=W) && (gy0+SH5<=H);
    const int fx = t & 31, fy = t >> 5;

    #pragma unroll
    for(int ci=0;ci<CIN;ci++){
        if(!SPLIT_IN){
            const float2* src = in + (size_t)(b*CIN+ci)*P;
            if(inter){
                #pragma unroll
                for(int ly=fy; ly<SH5; ly+=4){
                    const float4* grow = (const float4*)(src + (size_t)(gy0+ly)*W + gx0);
                    float4* srow = (float4*)&sm[ci][ly*SW5];
                    #pragma unroll
                    for(int j=fx; j<SW5/2; j+=32) srow[j] = grow[j];
                }
            } else {
                #pragma unroll
                for(int ly=fy; ly<SH5; ly+=4){
                    int gy = gy0+ly;
                    float2* srow = &sm[ci][ly*SW5];
                    #pragma unroll
                    for(int lx=fx; lx<SW5; lx+=32){
                        int gx = gx0+lx;
                        float2 v = make_float2(0.f, 0.f);
                        if((unsigned)gx<(unsigned)W && (unsigned)gy<(unsigned)H)
                            v = src[(size_t)gy*W+gx];
                        srow[lx] = v;
                    }
                }
            }
        } else {
            const float* cb = cs + (size_t)(b*CIN+ci)*P;
            const float* xb = xs + (size_t)(b*CIN+ci)*P;
            if(inter){
                #pragma unroll
                for(int ly=fy; ly<SH5; ly+=4){
                    const float* crow = cb + (size_t)(gy0+ly)*W + gx0;
                    const float* xrow = xb + (size_t)(gy0+ly)*W + gx0;
                    float2* srow = &sm[ci][ly*SW5];
                    #pragma unroll
                    for(int lx=fx; lx<SW5; lx+=32){
                        float c = crow[lx];
                        srow[lx] = make_float2(c, xrow[lx]*c);
                    }
                }
            } else {
                #pragma unroll
                for(int ly=fy; ly<SH5; ly+=4){
                    int gy = gy0+ly;
                    float2* srow = &sm[ci][ly*SW5];
                    #pragma unroll
                    for(int lx=fx; lx<SW5; lx+=32){
                        int gx = gx0+lx;
                        float c=0.f, d=0.f;
                        if((unsigned)gx<(unsigned)W && (unsigned)gy<(unsigned)H){
                            int o = gy*W+gx;
                            c = cb[o]; d = xb[o]*c;
                        }
                        srow[lx] = make_float2(c, d);
                    }
                }
            }
        }
    }
    __syncthreads();

    const int tx = (t & 15)*4;
    const int ty = (t >> 4)*2;

    ull acc[2][2][4];
    #pragma unroll
    for(int a=0;a<2;a++)
      #pragma unroll
      for(int dy=0;dy<2;dy++)
        #pragma unroll
        for(int dx=0;dx<4;dx++) acc[a][dy][dx]=0ull;

    // ky-outer, rolling two-row data buffer; each weight pair loaded ONCE.
    #pragma unroll
    for(int ci=0;ci<CIN;ci++){
        ull v[2][8];
        {
            const longlong2* p = (const longlong2*)&sm[ci][ty*SW5 + tx];
            #pragma unroll
            for(int j=0;j<4;j++){ longlong2 q=p[j]; v[0][2*j]=(ull)q.x; v[0][2*j+1]=(ull)q.y; }
        }
        #pragma unroll
        for(int ky=0;ky<5;ky++){
            const int cur = ky & 1, nxt = (ky+1) & 1;
            {
                const longlong2* p = (const longlong2*)&sm[ci][(ty+ky+1)*SW5 + tx];
                #pragma unroll
                for(int j=0;j<4;j++){ longlong2 q=p[j]; v[nxt][2*j]=(ull)q.x; v[nxt][2*j+1]=(ull)q.y; }
            }
            #pragma unroll
            for(int kx=0;kx<5;kx++){
                longlong2 wp = *(const longlong2*)&wpk2[(ci*25 + ky*5 + kx)*2];
                ull wa=(ull)wp.x, wb=(ull)wp.y;
                #pragma unroll
                for(int dx=0;dx<4;dx++){
                    acc[0][0][dx]=fma2(wa, v[cur][kx+dx], acc[0][0][dx]);
                    acc[1][0][dx]=fma2(wb, v[cur][kx+dx], acc[1][0][dx]);
                    acc[0][1][dx]=fma2(wa, v[nxt][kx+dx], acc[0][1][dx]);
                    acc[1][1][dx]=fma2(wb, v[nxt][kx+dx], acc[1][1][dx]);
                }
            }
        }
    }

    float rs0 = 1.0f/wex[0];
    float rs1 = 1.0f/wex[1];
    int gx = bx*TX5 + tx;
    int gyp = by*TY5 + ty;        // even; rows gyp, gyp+1
    if(gx < W && gyp < H){
        const int Wh = W>>1;
        const int Ph = Wh*(H>>1);
        #pragma unroll
        for(int a=0;a<2;a++){
            float rsa = a ? rs1 : rs0;
            float bia = wex[2+a];
            float rx[2][4], rc[2][4];
            #pragma unroll
            for(int dy=0;dy<2;dy++){
                #pragma unroll
                for(int j=0;j<2;j++){
                    float d0,n0,d1,n1;
                    unpack2(acc[a][dy][2*j],   d0, n0);
                    unpack2(acc[a][dy][2*j+1], d1, n1);
                    rx[dy][2*j]   = n0/(d0+EPSV)+bia;
                    rx[dy][2*j+1] = n1/(d1+EPSV)+bia;
                    rc[dy][2*j]   = d0*rsa;
                    rc[dy][2*j+1] = d1*rsa;
                }
                float4* dst = (float4*)(out + (size_t)(b*2+a)*P + (size_t)(gyp+dy)*W + gx);
                dst[0] = make_float4(rc[dy][0], rx[dy][0]*rc[dy][0],
                                     rc[dy][1], rx[dy][1]*rc[dy][1]);
                dst[1] = make_float4(rc[dy][2], rx[dy][2]*rc[dy][2],
                                     rc[dy][3], rx[dy][3]*rc[dy][3]);
            }
            if(POOL){
                float pc[2], px[2];
                #pragma unroll
                for(int cell=0;cell<2;cell++){
                    int c0 = 2*cell;
                    float bc = rc[0][c0],  bxv = rx[0][c0];
                    if(rc[0][c0+1]>bc){ bc=rc[0][c0+1]; bxv=rx[0][c0+1]; }
                    if(rc[1][c0]  >bc){ bc=rc[1][c0];   bxv=rx[1][c0];   }
                    if(rc[1][c0+1]>bc){ bc=rc[1][c0+1]; bxv=rx[1][c0+1]; }
                    pc[cell] = bc*0.25f;
                    px[cell] = bxv;
                }
                float4* pdst = (float4*)(outds + (size_t)(b*2+a)*Ph + (size_t)(gyp>>1)*Wh + (gx>>1));
                pdst[0] = make_float4(pc[0], px[0]*pc[0], pc[1], px[1]*pc[1]);
            }
        }
    }
}

// ---------------- tiled 3x3 cat nconv, interleaved I/O ---------------------
#define TX3 64
#define TY3 16
#define SW3 (TX3+2)   // 66
#define SH3 (TY3+2)   // 18

template<bool UP_FIRST, int WOFF, int LYR>
__global__ void __launch_bounds__(128,6)
k_nconv3t(const float2* __restrict__ na, const float2* __restrict__ ub,
          float2* __restrict__ out,
          int H, int W, int bpr, int bpc){
    __shared__ __align__(16) float2 sm[4][SH3*SW3];
    __shared__ __align__(16) ull wpk2[72];
    __shared__ float wex[4];

    const int t = threadIdx.x;
    const int P = H*W;
    const int Wh = W>>1, Ph = (W>>1)*(H>>1);

    for(int i=t;i<72;i+=128) wpk2[i]=g_wd[WOFF+i];
    if(t<2){ wex[t]=g_ws[2*LYR+t]; wex[2+t]=g_ws[16+2*LYR+t]; }

    int bx = blockIdx.x % bpr;
    int tmp = blockIdx.x / bpr;
    int by = tmp % bpc;
    int b  = tmp / bpc;
    int gx0 = bx*TX3 - 1;
    int gy0 = by*TY3 - 1;

    const bool inter = (gx0>=0) && (gy0>=0) && (gx0+SW3<=W) && (gy0+SH3<=H);
    const int fx = t & 31, fy = t >> 5;

    #pragma unroll
    for(int ci=0;ci<4;ci++){
        const bool fromUp = UP_FIRST ? (ci<2) : (ci>=2);
        const int ch = fromUp ? (UP_FIRST ? ci : ci-2) : (UP_FIRST ? ci-2 : ci);
        const float2* src = fromUp ? (ub + (size_t)(b*2+ch)*Ph) : (na + (size_t)(b*2+ch)*P);
        if(inter){
            #pragma unroll
            for(int ly=fy; ly<SH3; ly+=4){
                int gy = gy0+ly;
                float2* srow = &sm[ci][ly*SW3];
                if(fromUp){
                    const float2* grow = src + (size_t)(gy>>1)*Wh;
                    #pragma unroll
                    for(int lx=fx; lx<SW3; lx+=32)
                        srow[lx] = grow[(gx0+lx)>>1];
                } else {
                    const float2* grow = src + (size_t)gy*W + gx0;
                    #pragma unroll
                    for(int lx=fx; lx<SW3; lx+=32)
                        srow[lx] = grow[lx];
                }
            }
        } else {
            #pragma unroll
            for(int ly=fy; ly<SH3; ly+=4){
                int gy = gy0+ly;
                float2* srow = &sm[ci][ly*SW3];
                #pragma unroll
                for(int lx=fx; lx<SW3; lx+=32){
                    int gx = gx0+lx;
                    float2 v = make_float2(0.f, 0.f);
                    if((unsigned)gx<(unsigned)W && (unsigned)gy<(unsigned)H)
                        v = fromUp ? src[(size_t)(gy>>1)*Wh + (gx>>1)]
                                   : src[(size_t)gy*W + gx];
                    srow[lx] = v;
                }
            }
        }
    }
    __syncthreads();

    const int tx = (t & 15)*4;
    const int ty = (t >> 4)*2;

    ull acc[2][2][4];
    #pragma unroll
    for(int a=0;a<2;a++)
      #pragma unroll
      for(int dy=0;dy<2;dy++)
        #pragma unroll
        for(int dx=0;dx<4;dx++) acc[a][dy][dx]=0ull;

    #pragma unroll
    for(int ci=0;ci<4;ci++){
        ull v[2][6];
        {
            const longlong2* p = (const longlong2*)&sm[ci][ty*SW3 + tx];
            #pragma unroll
            for(int j=0;j<3;j++){ longlong2 q=p[j]; v[0][2*j]=(ull)q.x; v[0][2*j+1]=(ull)q.y; }
        }
        #pragma unroll
        for(int ky=0;ky<3;ky++){
            const int cur = ky & 1, nxt = (ky+1) & 1;
            {
                const longlong2* p = (const longlong2*)&sm[ci][(ty+ky+1)*SW3 + tx];
                #pragma unroll
                for(int j=0;j<3;j++){ longlong2 q=p[j]; v[nxt][2*j]=(ull)q.x; v[nxt][2*j+1]=(ull)q.y; }
            }
            #pragma unroll
            for(int kx=0;kx<3;kx++){
                longlong2 wp = *(const longlong2*)&wpk2[(ci*9 + ky*3 + kx)*2];
                ull wa=(ull)wp.x, wb=(ull)wp.y;
                #pragma unroll
                for(int dx=0;dx<4;dx++){
                    acc[0][0][dx]=fma2(wa, v[cur][kx+dx], acc[0][0][dx]);
                    acc[1][0][dx]=fma2(wb, v[cur][kx+dx], acc[1][0][dx]);
                    acc[0][1][dx]=fma2(wa, v[nxt][kx+dx], acc[0][1][dx]);
                    acc[1][1][dx]=fma2(wb, v[nxt][kx+dx], acc[1][1][dx]);
                }
            }
        }
    }

    float rs0 = 1.0f/wex[0];
    float rs1 = 1.0f/wex[1];
    float bi0 = wex[2];
    float bi1 = wex[3];
    int gx = bx*TX3 + tx;
    if(gx < W){
        #pragma unroll
        for(int dy=0;dy<2;dy++){
            int gy = by*TY3 + ty + dy;
            if(gy>=H) continue;
            #pragma unroll
            for(int a=0;a<2;a++){
                float d0,n0,d1,n1,d2,n2,d3,n3;
                unpack2(acc[a][dy][0], d0, n0);
                unpack2(acc[a][dy][1], d1, n1);
                unpack2(acc[a][dy][2], d2, n2);
                unpack2(acc[a][dy][3], d3, n3);
                float bia = a ? bi1 : bi0;
                float rsa = a ? rs1 : rs0;
                float x0v = n0/(d0+EPSV)+bia, x1v = n1/(d1+EPSV)+bia;
                float x2v = n2/(d2+EPSV)+bia, x3v = n3/(d3+EPSV)+bia;
                float c0v = d0*rsa, c1v = d1*rsa, c2v = d2*rsa, c3v = d3*rsa;
                float4* dst = (float4*)(out + (size_t)(b*2+a)*P + (size_t)gy*W + gx);
                dst[0] = make_float4(c0v, x0v*c0v, c1v, x1v*c1v);
                dst[1] = make_float4(c2v, x2v*c2v, c3v, x3v*c3v);
            }
        }
    }
}

// final 1x1 nconv: interleaved in, plain planes out
__global__ void k_nconv1x1(const float2* __restrict__ in,
                           float* __restrict__ xout, float* __restrict__ cout_){
    int idx = blockIdx.x*blockDim.x + threadIdx.x;
    const int Q = P0/4;
    if(idx >= BB*Q) return;
    int q = idx % Q;
    int b = idx / Q;
    const float4* p0 = (const float4*)(in + (size_t)(b*2+0)*P0) + 2*q;
    const float4* p1 = (const float4*)(in + (size_t)(b*2+1)*P0) + 2*q;
    float4 u0 = p0[0], u1 = p0[1];
    float4 v0 = p1[0], v1 = p1[1];
    float w0,w1,hi;
    unpack2(g_wd[466], w0, hi);
    unpack2(g_wd[468], w1, hi);
    float rsum = 1.0f/g_ws[12];
    float bi = g_ws[28];
    float c0[4] = {u0.x, u0.z, u1.x, u1.z};
    float d0[4] = {u0.y, u0.w, u1.y, u1.w};
    float c1[4] = {v0.x, v0.z, v1.x, v1.z};
    float d1[4] = {v0.y, v0.w, v1.y, v1.w};
    float4 XO, CO;
    #pragma unroll
    for(int k=0;k<4;k++){
        float den = w0*c0[k] + w1*c1[k];
        float nom = w0*d0[k] + w1*d1[k];
        ((float*)&XO)[k] = nom/(den+EPSV) + bi;
        ((float*)&CO)[k] = den*rsum;
    }
    ((float4*)(xout  + (size_t)b*P0))[q] = XO;
    ((float4*)(cout_ + (size_t)b*P0))[q] = CO;
}

extern "C" void kernel_launch(void* const* d_in, const int* in_sizes, int n_in,
                              void* d_out, int out_size){
    const float* x0 = (const float*)d_in[0];
    const float* c0 = (const float*)d_in[1];
    const float* w1 = (const float*)d_in[2];  const float* b1 = (const float*)d_in[3];
    const float* w2 = (const float*)d_in[4];  const float* b2 = (const float*)d_in[5];
    const float* w3 = (const float*)d_in[6];  const float* b3 = (const float*)d_in[7];
    const float* w4 = (const float*)d_in[8];  const float* b4 = (const float*)d_in[9];
    const float* w5 = (const float*)d_in[10]; const float* b5 = (const float*)d_in[11];
    const float* w6 = (const float*)d_in[12]; const float* b6 = (const float*)d_in[13];
    const float* w7 = (const float*)d_in[14]; const float* b7 = (const float*)d_in[15];

    float2* S = nullptr;  cudaGetSymbolAddress((void**)&S,  g_scratch);

    float2 *A  = S,        *Bv = S + M0,     *T1 = S + 2*M0;
    float2 *HA = S + 3*M0, *HB = HA + M1,    *T2 = HA + 2*M1;
    float2 *Q  = HA + 3*M1,*T3 = Q + M2,     *T34= Q + 2*M2;
    float2 *E  = Q + 3*M2, *T4 = E + M3;

    auto tiles = [&](int H, int W, int &bpr, int &bpc)->int{
        bpr = (W + TX5 - 1)/TX5; bpc = (H + TY5 - 1)/TY5;
        return bpr*bpc*BB;
    };

    k_prep<<<1,128>>>(w1,b1,w2,b2,w3,b3,w4,b4,w5,b5,w6,b6,w7,b7);

    int bpr, bpc, g;

    // encoder full res (3rd layer fuses pool -> level-1 inputs)
    g = tiles(H0,W0,bpr,bpc);
    k_nconv5t<1,0,0,false,true>   <<<g,128>>>(nullptr, x0, c0, A, nullptr, H0, W0, bpr, bpc);
    k_nconv5t<2,50,1,false,false> <<<g,128>>>(A, nullptr, nullptr, Bv, nullptr, H0, W0, bpr, bpc);
    k_nconv5t<2,150,2,true,false> <<<g,128>>>(Bv, nullptr, nullptr, T1, HA, H0, W0, bpr, bpc);

    // level 1 (2nd layer fuses pool -> level-2 inputs)
    g = tiles(H1,W1,bpr,bpc);
    k_nconv5t<2,50,1,false,false> <<<g,128>>>(HA, nullptr, nullptr, HB, nullptr, H1, W1, bpr, bpc);
    k_nconv5t<2,150,2,true,false> <<<g,128>>>(HB, nullptr, nullptr, T2, Q, H1, W1, bpr, bpc);

    // level 2 (fuses pool -> level-3 inputs)
    g = tiles(H2,W2,bpr,bpc);
    k_nconv5t<2,50,1,true,false>  <<<g,128>>>(Q, nullptr, nullptr, T3, E, H2, W2, bpr, bpc);

    // level 3
    g = tiles(H3,W3,bpr,bpc);
    k_nconv5t<2,50,1,false,false> <<<g,128>>>(E, nullptr, nullptr, T4, nullptr, H3, W3, bpr, bpc);

    // decoder
    g = tiles(H2,W2,bpr,bpc);
    k_nconv3t<false,250,3><<<g,128>>>(T3, T4,  T34, H2, W2, bpr, bpc);
    g = tiles(H1,W1,bpr,bpc);
    k_nconv3t<false,322,4><<<g,128>>>(T2, T34, HA,  H1, W1, bpr, bpc);
    g = tiles(H0,W0,bpr,bpc);
    k_nconv3t<true,394,5> <<<g,128>>>(T1, HA,  A,   H0, W0, bpr, bpc);

    float* out = (float*)d_out;
    k_nconv1x1<<<(BB*(P0/4)+255)/256,256>>>(A, out, out + (size_t)BB*P0);
}

// round 11
// speedup vs baseline: 1.6159x; 1.0483x over previous
#include <cuda_runtime.h>
#include <math.h>

#define EPSV 1e-20f

#define BB 16
#define H0 352
#define W0 1216
#define H1 176
#define W1 608
#define H2 88
#define W2 304
#define H3 44
#define W3 152

#define P0 (H0*W0)
#define P1 (H1*W1)
#define P2 (H2*W2)
#define P3 (H3*W3)

// float2 element counts per interleaved (c, x*c) tensor
#define M0 ((size_t)BB*2*P0)
#define M1 ((size_t)BB*2*P1)
#define M2 ((size_t)BB*2*P2)
#define M3 ((size_t)BB*2*P3)

typedef unsigned long long ull;

__device__ __align__(16) float2 g_scratch[3*M0 + 3*M1 + 3*M2 + 2*M3];
__device__ ull   g_wd[480];
__device__ float g_ws[32];

// dup-pair weight layout (ull units):
// w1:0(50) w2:50(100) w3:150(100) w4:250(72) w5:322(72) w6:394(72) w7:466(4)
// entry: OFF + (ci*K + k)*2 + cout
// g_ws: sums at [2*lyr + co], biases at [16 + 2*lyr + co]

__device__ __forceinline__ ull fma2(ull a, ull b, ull c){
    ull d; asm("fma.rn.f32x2 %0, %1, %2, %3;" : "=l"(d) : "l"(a), "l"(b), "l"(c)); return d;
}
__device__ __forceinline__ void unpack2(ull v, float &a, float &b){
    asm("mov.b64 {%0,%1}, %2;" : "=f"(a), "=f"(b) : "l"(v));
}
__device__ __forceinline__ ull dupf(float w){
    float2 f2 = make_float2(w, w);
    return *(ull*)&f2;
}
__device__ __forceinline__ float sp10(float p){
    float z = 10.0f * p;
    float r = (z > 20.0f) ? z : log1pf(expf(z));
    return r * 0.1f;
}

__global__ void k_prep(const float* __restrict__ w1, const float* __restrict__ b1,
                       const float* __restrict__ w2, const float* __restrict__ b2,
                       const float* __restrict__ w3, const float* __restrict__ b3,
                       const float* __restrict__ w4, const float* __restrict__ b4,
                       const float* __restrict__ w5, const float* __restrict__ b5,
                       const float* __restrict__ w6, const float* __restrict__ b6,
                       const float* __restrict__ w7, const float* __restrict__ b7){
    const float* wp[7]={w1,w2,w3,w4,w5,w6,w7};
    const float* bp[7]={b1,b2,b3,b4,b5,b6,b7};
    const int cin[7]={1,2,2,4,4,4,2};
    const int kk [7]={25,25,25,9,9,9,1};
    const int co [7]={2,2,2,2,2,2,1};
    const int off[7]={0,50,150,250,322,394,466};
    int t=threadIdx.x;
    for(int l=0;l<7;l++){
        int n=cin[l]*kk[l];
        int tot=n*co[l];
        for(int i=t;i<tot;i+=blockDim.x){
            int c=i/n, e=i%n;
            g_wd[off[l]+e*2+c]=dupf(sp10(wp[l][c*n+e]));
        }
    }
    __syncthreads();
    if(t==0){
        for(int l=0;l<7;l++){
            int n=cin[l]*kk[l];
            for(int c=0;c<co[l];c++){
                float s=0.f;
                for(int e=0;e<n;e++){ float lo,hi; unpack2(g_wd[off[l]+e*2+c],lo,hi); s+=lo; }
                g_ws[2*l+c]=s;
                g_ws[16+2*l+c]=bp[l][c];
            }
        }
    }
}

// ---------------- tiled 5x5 nconv, interleaved I/O, opt. fused pool --------
#define TX5 64
#define TY5 16
#define SW5 (TX5+4)   // 68
#define SH5 (TY5+4)   // 20

template<int CIN, int WOFF, int LYR, bool POOL, bool SPLIT_IN>
__global__ void __launch_bounds__(128,6)
k_nconv5t(const float2* __restrict__ in, const float* __restrict__ xs, const float* __restrict__ cs,
          float2* __restrict__ out, float2* __restrict__ outds,
          int H, int W, int bpr, int bpc){
    __shared__ __align__(16) float2 sm[CIN][SH5*SW5];
    __shared__ __align__(16) ull wpk2[2*CIN*25];
    __shared__ float wex[4];

    const int t = threadIdx.x;
    const int P = H*W;

    for(int i=t;i<2*CIN*25;i+=128) wpk2[i]=g_wd[WOFF+i];
    if(t<2){ wex[t]=g_ws[2*LYR+t]; wex[2+t]=g_ws[16+2*LYR+t]; }

    int bx = blockIdx.x % bpr;
    int tmp = blockIdx.x / bpr;
    int by = tmp % bpc;
    int b  = tmp / bpc;
    int gx0 = bx*TX5 - 2;   // always even
    int gy0 = by*TY5 - 2;

    const bool inter = (gx0>=0) && (gy0>=0) && (gx0+SW5<=W) && (gy0+SH5<=H);
    const int fx = t & 31, fy = t >> 5;

    #pragma unroll
    for(int ci=0;ci<CIN;ci++){
        if(!SPLIT_IN){
            const float2* src = in + (size_t)(b*CIN+ci)*P;
            if(inter){
                #pragma unroll
                for(int ly=fy; ly<SH5; ly+=4){
                    const float4* grow = (const float4*)(src + (size_t)(gy0+ly)*W + gx0);
                    float4* srow = (float4*)&sm[ci][ly*SW5];
                    #pragma unroll
                    for(int j=fx; j<SW5/2; j+=32) srow[j] = grow[j];
                }
            } else {
                #pragma unroll
                for(int ly=fy; ly<SH5; ly+=4){
                    int gy = gy0+ly;
                    float2* srow = &sm[ci][ly*SW5];
                    #pragma unroll
                    for(int lx=fx; lx<SW5; lx+=32){
                        int gx = gx0+lx;
                        float2 v = make_float2(0.f, 0.f);
                        if((unsigned)gx<(unsigned)W && (unsigned)gy<(unsigned)H)
                            v = src[(size_t)gy*W+gx];
                        srow[lx] = v;
                    }
                }
            }
        } else {
            const float* cb = cs + (size_t)(b*CIN+ci)*P;
            const float* xb = xs + (size_t)(b*CIN+ci)*P;
            if(inter){
                #pragma unroll
                for(int ly=fy; ly<SH5; ly+=4){
                    const float* crow = cb + (size_t)(gy0+ly)*W + gx0;
                    const float* xrow = xb + (size_t)(gy0+ly)*W + gx0;
                    float2* srow = &sm[ci][ly*SW5];
                    #pragma unroll
                    for(int lx=fx; lx<SW5; lx+=32){
                        float c = crow[lx];
                        srow[lx] = make_float2(c, xrow[lx]*c);
                    }
                }
            } else {
                #pragma unroll
                for(int ly=fy; ly<SH5; ly+=4){
                    int gy = gy0+ly;
                    float2* srow = &sm[ci][ly*SW5];
                    #pragma unroll
                    for(int lx=fx; lx<SW5; lx+=32){
                        int gx = gx0+lx;
                        float c=0.f, d=0.f;
                        if((unsigned)gx<(unsigned)W && (unsigned)gy<(unsigned)H){
                            int o = gy*W+gx;
                            c = cb[o]; d = xb[o]*c;
                        }
                        srow[lx] = make_float2(c, d);
                    }
                }
            }
        }
    }
    __syncthreads();

    const int tx = (t & 15)*4;
    const int ty = (t >> 4)*2;

    ull acc[2][2][4];
    #pragma unroll
    for(int a=0;a<2;a++)
      #pragma unroll
      for(int dy=0;dy<2;dy++)
        #pragma unroll
        for(int dx=0;dx<4;dx++) acc[a][dy][dx]=0ull;

    // ky-outer, rolling two-row data buffer; each weight pair loaded ONCE.
    #pragma unroll
    for(int ci=0;ci<CIN;ci++){
        ull v[2][8];
        {
            const longlong2* p = (const longlong2*)&sm[ci][ty*SW5 + tx];
            #pragma unroll
            for(int j=0;j<4;j++){ longlong2 q=p[j]; v[0][2*j]=(ull)q.x; v[0][2*j+1]=(ull)q.y; }
        }
        #pragma unroll
        for(int ky=0;ky<5;ky++){
            const int cur = ky & 1, nxt = (ky+1) & 1;
            {
                const longlong2* p = (const longlong2*)&sm[ci][(ty+ky+1)*SW5 + tx];
                #pragma unroll
                for(int j=0;j<4;j++){ longlong2 q=p[j]; v[nxt][2*j]=(ull)q.x; v[nxt][2*j+1]=(ull)q.y; }
            }
            #pragma unroll
            for(int kx=0;kx<5;kx++){
                longlong2 wp = *(const longlong2*)&wpk2[(ci*25 + ky*5 + kx)*2];
                ull wa=(ull)wp.x, wb=(ull)wp.y;
                #pragma unroll
                for(int dx=0;dx<4;dx++){
                    acc[0][0][dx]=fma2(wa, v[cur][kx+dx], acc[0][0][dx]);
                    acc[1][0][dx]=fma2(wb, v[cur][kx+dx], acc[1][0][dx]);
                    acc[0][1][dx]=fma2(wa, v[nxt][kx+dx], acc[0][1][dx]);
                    acc[1][1][dx]=fma2(wb, v[nxt][kx+dx], acc[1][1][dx]);
                }
            }
        }
    }

    float rs0 = 1.0f/wex[0];
    float rs1 = 1.0f/wex[1];
    int gx = bx*TX5 + tx;
    int gyp = by*TY5 + ty;        // even; rows gyp, gyp+1
    if(gx < W && gyp < H){
        const int Wh = W>>1;
        const int Ph = Wh*(H>>1);
        #pragma unroll
        for(int a=0;a<2;a++){
            float rsa = a ? rs1 : rs0;
            float bia = wex[2+a];
            float rx[2][4], rc[2][4];
            #pragma unroll
            for(int dy=0;dy<2;dy++){
                #pragma unroll
                for(int j=0;j<2;j++){
                    float d0,n0,d1,n1;
                    unpack2(acc[a][dy][2*j],   d0, n0);
                    unpack2(acc[a][dy][2*j+1], d1, n1);
                    rx[dy][2*j]   = n0/(d0+EPSV)+bia;
                    rx[dy][2*j+1] = n1/(d1+EPSV)+bia;
                    rc[dy][2*j]   = d0*rsa;
                    rc[dy][2*j+1] = d1*rsa;
                }
                float4* dst = (float4*)(out + (size_t)(b*2+a)*P + (size_t)(gyp+dy)*W + gx);
                dst[0] = make_float4(rc[dy][0], rx[dy][0]*rc[dy][0],
                                     rc[dy][1], rx[dy][1]*rc[dy][1]);
                dst[1] = make_float4(rc[dy][2], rx[dy][2]*rc[dy][2],
                                     rc[dy][3], rx[dy][3]*rc[dy][3]);
            }
            if(POOL){
                float pc[2], px[2];
                #pragma unroll
                for(int cell=0;cell<2;cell++){
                    int c0 = 2*cell;
                    float bc = rc[0][c0],  bxv = rx[0][c0];
                    if(rc[0][c0+1]>bc){ bc=rc[0][c0+1]; bxv=rx[0][c0+1]; }
                    if(rc[1][c0]  >bc){ bc=rc[1][c0];   bxv=rx[1][c0];   }
                    if(rc[1][c0+1]>bc){ bc=rc[1][c0+1]; bxv=rx[1][c0+1]; }
                    pc[cell] = bc*0.25f;
                    px[cell] = bxv;
                }
                float4* pdst = (float4*)(outds + (size_t)(b*2+a)*Ph + (size_t)(gyp>>1)*Wh + (gx>>1));
                pdst[0] = make_float4(pc[0], px[0]*pc[0], pc[1], px[1]*pc[1]);
            }
        }
    }
}

// ---------------- tiled 3x3 cat nconv, interleaved I/O, opt. fused 1x1 -----
#define TX3 64
#define TY3 16
#define SW3 (TX3+2)   // 66
#define SH3 (TY3+2)   // 18

template<bool UP_FIRST, int WOFF, int LYR, bool FUSE_OUT>
__global__ void __launch_bounds__(128,6)
k_nconv3t(const float2* __restrict__ na, const float2* __restrict__ ub,
          float2* __restrict__ out,
          float* __restrict__ xof, float* __restrict__ cof,
          int H, int W, int bpr, int bpc){
    __shared__ __align__(16) float2 sm[4][SH3*SW3];
    __shared__ __align__(16) ull wpk2[72];
    __shared__ float wex[8];

    const int t = threadIdx.x;
    const int P = H*W;
    const int Wh = W>>1, Ph = (W>>1)*(H>>1);

    for(int i=t;i<72;i+=128) wpk2[i]=g_wd[WOFF+i];
    if(t<2){ wex[t]=g_ws[2*LYR+t]; wex[2+t]=g_ws[16+2*LYR+t]; }
    if(FUSE_OUT && t==0){
        float lo, hi;
        unpack2(g_wd[466], lo, hi); wex[4]=lo;       // w7_0
        unpack2(g_wd[468], lo, hi); wex[5]=lo;       // w7_1
        wex[6]=1.0f/g_ws[12];                        // 1/sum7
        wex[7]=g_ws[28];                             // bias7
    }

    int bx = blockIdx.x % bpr;
    int tmp = blockIdx.x / bpr;
    int by = tmp % bpc;
    int b  = tmp / bpc;
    int gx0 = bx*TX3 - 1;
    int gy0 = by*TY3 - 1;

    const bool inter = (gx0>=0) && (gy0>=0) && (gx0+SW3<=W) && (gy0+SH3<=H);
    const int fx = t & 31, fy = t >> 5;

    #pragma unroll
    for(int ci=0;ci<4;ci++){
        const bool fromUp = UP_FIRST ? (ci<2) : (ci>=2);
        const int ch = fromUp ? (UP_FIRST ? ci : ci-2) : (UP_FIRST ? ci-2 : ci);
        const float2* src = fromUp ? (ub + (size_t)(b*2+ch)*Ph) : (na + (size_t)(b*2+ch)*P);
        if(inter){
            #pragma unroll
            for(int ly=fy; ly<SH3; ly+=4){
                int gy = gy0+ly;
                float2* srow = &sm[ci][ly*SW3];
                if(fromUp){
                    const float2* grow = src + (size_t)(gy>>1)*Wh;
                    #pragma unroll
                    for(int lx=fx; lx<SW3; lx+=32)
                        srow[lx] = grow[(gx0+lx)>>1];
                } else {
                    const float2* grow = src + (size_t)gy*W + gx0;
                    #pragma unroll
                    for(int lx=fx; lx<SW3; lx+=32)
                        srow[lx] = grow[lx];
                }
            }
        } else {
            #pragma unroll
            for(int ly=fy; ly<SH3; ly+=4){
                int gy = gy0+ly;
                float2* srow = &sm[ci][ly*SW3];
                #pragma unroll
                for(int lx=fx; lx<SW3; lx+=32){
                    int gx = gx0+lx;
                    float2 v = make_float2(0.f, 0.f);
                    if((unsigned)gx<(unsigned)W && (unsigned)gy<(unsigned)H)
                        v = fromUp ? src[(size_t)(gy>>1)*Wh + (gx>>1)]
                                   : src[(size_t)gy*W + gx];
                    srow[lx] = v;
                }
            }
        }
    }
    __syncthreads();

    const int tx = (t & 15)*4;
    const int ty = (t >> 4)*2;

    ull acc[2][2][4];
    #pragma unroll
    for(int a=0;a<2;a++)
      #pragma unroll
      for(int dy=0;dy<2;dy++)
        #pragma unroll
        for(int dx=0;dx<4;dx++) acc[a][dy][dx]=0ull;

    #pragma unroll
    for(int ci=0;ci<4;ci++){
        ull v[2][6];
        {
            const longlong2* p = (const longlong2*)&sm[ci][ty*SW3 + tx];
            #pragma unroll
            for(int j=0;j<3;j++){ longlong2 q=p[j]; v[0][2*j]=(ull)q.x; v[0][2*j+1]=(ull)q.y; }
        }
        #pragma unroll
        for(int ky=0;ky<3;ky++){
            const int cur = ky & 1, nxt = (ky+1) & 1;
            {
                const longlong2* p = (const longlong2*)&sm[ci][(ty+ky+1)*SW3 + tx];
                #pragma unroll
                for(int j=0;j<3;j++){ longlong2 q=p[j]; v[nxt][2*j]=(ull)q.x; v[nxt][2*j+1]=(ull)q.y; }
            }
            #pragma unroll
            for(int kx=0;kx<3;kx++){
                longlong2 wp = *(const longlong2*)&wpk2[(ci*9 + ky*3 + kx)*2];
                ull wa=(ull)wp.x, wb=(ull)wp.y;
                #pragma unroll
                for(int dx=0;dx<4;dx++){
                    acc[0][0][dx]=fma2(wa, v[cur][kx+dx], acc[0][0][dx]);
                    acc[1][0][dx]=fma2(wb, v[cur][kx+dx], acc[1][0][dx]);
                    acc[0][1][dx]=fma2(wa, v[nxt][kx+dx], acc[0][1][dx]);
                    acc[1][1][dx]=fma2(wb, v[nxt][kx+dx], acc[1][1][dx]);
                }
            }
        }
    }

    float rs0 = 1.0f/wex[0];
    float rs1 = 1.0f/wex[1];
    float bi0 = wex[2];
    float bi1 = wex[3];
    int gx = bx*TX3 + tx;
    if(gx < W){
        #pragma unroll
        for(int dy=0;dy<2;dy++){
            int gy = by*TY3 + ty + dy;
            if(gy>=H) continue;
            float xc[2][4], cc[2][4];
            #pragma unroll
            for(int a=0;a<2;a++){
                float d0,n0,d1,n1,d2,n2,d3,n3;
                unpack2(acc[a][dy][0], d0, n0);
                unpack2(acc[a][dy][1], d1, n1);
                unpack2(acc[a][dy][2], d2, n2);
                unpack2(acc[a][dy][3], d3, n3);
                float bia = a ? bi1 : bi0;
                float rsa = a ? rs1 : rs0;
                xc[a][0] = n0/(d0+EPSV)+bia; xc[a][1] = n1/(d1+EPSV)+bia;
                xc[a][2] = n2/(d2+EPSV)+bia; xc[a][3] = n3/(d3+EPSV)+bia;
                cc[a][0] = d0*rsa; cc[a][1] = d1*rsa;
                cc[a][2] = d2*rsa; cc[a][3] = d3*rsa;
            }
            if(!FUSE_OUT){
                #pragma unroll
                for(int a=0;a<2;a++){
                    float4* dst = (float4*)(out + (size_t)(b*2+a)*P + (size_t)gy*W + gx);
                    dst[0] = make_float4(cc[a][0], xc[a][0]*cc[a][0],
                                         cc[a][1], xc[a][1]*cc[a][1]);
                    dst[1] = make_float4(cc[a][2], xc[a][2]*cc[a][2],
                                         cc[a][3], xc[a][3]*cc[a][3]);
                }
            } else {
                float w70 = wex[4], w71 = wex[5], rs7 = wex[6], bi7 = wex[7];
                float4 XO, CO;
                #pragma unroll
                for(int k=0;k<4;k++){
                    float den = w70*cc[0][k] + w71*cc[1][k];
                    float nom = w70*xc[0][k]*cc[0][k] + w71*xc[1][k]*cc[1][k];
                    ((float*)&XO)[k] = nom/(den+EPSV) + bi7;
                    ((float*)&CO)[k] = den*rs7;
                }
                size_t o = (size_t)b*P + (size_t)gy*W + gx;
                *(float4*)&xof[o] = XO;
                *(float4*)&cof[o] = CO;
            }
        }
    }
}

extern "C" void kernel_launch(void* const* d_in, const int* in_sizes, int n_in,
                              void* d_out, int out_size){
    const float* x0 = (const float*)d_in[0];
    const float* c0 = (const float*)d_in[1];
    const float* w1 = (const float*)d_in[2];  const float* b1 = (const float*)d_in[3];
    const float* w2 = (const float*)d_in[4];  const float* b2 = (const float*)d_in[5];
    const float* w3 = (const float*)d_in[6];  const float* b3 = (const float*)d_in[7];
    const float* w4 = (const float*)d_in[8];  const float* b4 = (const float*)d_in[9];
    const float* w5 = (const float*)d_in[10]; const float* b5 = (const float*)d_in[11];
    const float* w6 = (const float*)d_in[12]; const float* b6 = (const float*)d_in[13];
    const float* w7 = (const float*)d_in[14]; const float* b7 = (const float*)d_in[15];

    float2* S = nullptr;  cudaGetSymbolAddress((void**)&S,  g_scratch);

    float2 *A  = S,        *Bv = S + M0,     *T1 = S + 2*M0;
    float2 *HA = S + 3*M0, *HB = HA + M1,    *T2 = HA + 2*M1;
    float2 *Q  = HA + 3*M1,*T3 = Q + M2,     *T34= Q + 2*M2;
    float2 *E  = Q + 3*M2, *T4 = E + M3;

    auto tiles = [&](int H, int W, int &bpr, int &bpc)->int{
        bpr = (W + TX5 - 1)/TX5; bpc = (H + TY5 - 1)/TY5;
        return bpr*bpc*BB;
    };

    k_prep<<<1,128>>>(w1,b1,w2,b2,w3,b3,w4,b4,w5,b5,w6,b6,w7,b7);

    int bpr, bpc, g;

    // encoder full res (3rd layer fuses pool -> level-1 inputs)
    g = tiles(H0,W0,bpr,bpc);
    k_nconv5t<1,0,0,false,true>   <<<g,128>>>(nullptr, x0, c0, A, nullptr, H0, W0, bpr, bpc);
    k_nconv5t<2,50,1,false,false> <<<g,128>>>(A, nullptr, nullptr, Bv, nullptr, H0, W0, bpr, bpc);
    k_nconv5t<2,150,2,true,false> <<<g,128>>>(Bv, nullptr, nullptr, T1, HA, H0, W0, bpr, bpc);

    // level 1 (2nd layer fuses pool -> level-2 inputs)
    g = tiles(H1,W1,bpr,bpc);
    k_nconv5t<2,50,1,false,false> <<<g,128>>>(HA, nullptr, nullptr, HB, nullptr, H1, W1, bpr, bpc);
    k_nconv5t<2,150,2,true,false> <<<g,128>>>(HB, nullptr, nullptr, T2, Q, H1, W1, bpr, bpc);

    // level 2 (fuses pool -> level-3 inputs)
    g = tiles(H2,W2,bpr,bpc);
    k_nconv5t<2,50,1,true,false>  <<<g,128>>>(Q, nullptr, nullptr, T3, E, H2, W2, bpr, bpc);

    // level 3
    g = tiles(H3,W3,bpr,bpc);
    k_nconv5t<2,50,1,false,false> <<<g,128>>>(E, nullptr, nullptr, T4, nullptr, H3, W3, bpr, bpc);

    // decoder (last stage fuses the final 1x1 nconv directly into d_out)
    float* out = (float*)d_out;
    g = tiles(H2,W2,bpr,bpc);
    k_nconv3t<false,250,3,false><<<g,128>>>(T3, T4,  T34, nullptr, nullptr, H2, W2, bpr, bpc);
    g = tiles(H1,W1,bpr,bpc);
    k_nconv3t<false,322,4,false><<<g,128>>>(T2, T34, HA,  nullptr, nullptr, H1, W1, bpr, bpc);
    g = tiles(H0,W0,bpr,bpc);
    k_nconv3t<true,394,5,true>  <<<g,128>>>(T1, HA,  nullptr,
                                            out, out + (size_t)BB*P0, H0, W0, bpr, bpc);
}